// round 5
// baseline (speedup 1.0000x reference)
#include <cuda_runtime.h>
#include <math.h>
#include <stdint.h>

#define BB    128
#define HID   512
#define G4    2048
#define VOCAB 1000
#define TT    256
#define KDIM  512
#define NBLK  128
#define NTHR  512

// smem layout (floats): [0, 18432) hs(512x20) UNION red(512x36); [18432, 20992) gt(128x20)
#define RED_F   18432
#define GT_F    2560
#define SMEM_B  ((RED_F + GT_F) * 4)

typedef unsigned long long ull;

__device__ float g_base[BB * G4];
__device__ float g_P[VOCAB * G4];
__device__ float g_h[2][BB * HID];
__device__ float g_c[BB * HID];
__device__ ull   g_pk[2][BB];
__device__ unsigned g_bcnt[8];
__device__ volatile unsigned g_bgen[8];

__device__ __forceinline__ ull splat2(float x) {
    ull r; asm("mov.b64 %0, {%1, %1};" : "=l"(r) : "f"(x)); return r;
}
__device__ __forceinline__ void fma2(ull& d, ull a, ull b) {
    asm("fma.rn.f32x2 %0, %1, %2, %0;" : "+l"(d) : "l"(a), "l"(b));
}
__device__ __forceinline__ float2 unpack2(ull x) {
    float lo, hi; asm("mov.b64 {%0, %1}, %2;" : "=f"(lo), "=f"(hi) : "l"(x));
    return make_float2(lo, hi);
}
__device__ __forceinline__ unsigned fkey(float f) {
    unsigned b = __float_as_uint(f);
    return (b & 0x80000000u) ? ~b : (b | 0x80000000u);
}
__device__ __forceinline__ float sigf(float x) { return 1.f / (1.f + expf(-x)); }

__device__ __forceinline__ void group_sync(int bt) {
    __syncthreads();
    if (threadIdx.x == 0) {
        unsigned g = g_bgen[bt];
        __threadfence();
        if (atomicAdd(&g_bcnt[bt], 1u) == 15u) {
            g_bcnt[bt] = 0u;
            __threadfence();
            g_bgen[bt] = g + 1u;
        } else {
            while (g_bgen[bt] == g) { }
        }
        __threadfence();           // CCTL.IVALL: invalidate L1 before consuming peers' data
    }
    __syncthreads();
}

__global__ void k_init(const float* __restrict__ ctx, const int* __restrict__ sid) {
    int i = blockIdx.x * 256 + threadIdx.x;          // 65536
    g_h[0][i] = ctx[i];
    g_c[i] = 0.f;
    if (i < BB) {
        g_pk[0][i] = 0ull;
        g_pk[1][i] = (ull)(unsigned)(~(unsigned)sid[0]);
    }
    if (i < 8) { g_bcnt[i] = 0u; g_bgen[i] = 0u; }
}

// one-time precompute: C[M,2048] = A[M,512] @ W^T (+b1+b2). tile 32m x 128n.
__global__ __launch_bounds__(256) void k_gemm(
    const float* __restrict__ A, int M,
    const float* __restrict__ W, int ws_,
    const float* __restrict__ b1, const float* __restrict__ b2, int dst)
{
    __shared__ __align__(16) float As[32][32];
    __shared__ __align__(16) float Ws[32][128];
    float* __restrict__ C = dst ? g_P : g_base;
    const int tid = threadIdx.x, txn = tid & 15, tym = tid >> 4;
    const int m0 = blockIdx.x * 32, n0 = blockIdx.y * 128;
    ull acc[2][4];
#pragma unroll
    for (int m = 0; m < 2; m++)
#pragma unroll
        for (int j = 0; j < 4; j++) acc[m][j] = 0ull;

    for (int k0 = 0; k0 < KDIM; k0 += 32) {
        __syncthreads();
#pragma unroll
        for (int i = 0; i < 4; i++) {
            int idx = i * 256 + tid, r = idx >> 3, kq = idx & 7;
            float4 v = *(const float4*)&W[(size_t)(n0 + r) * ws_ + k0 + kq * 4];
            int sw = r ^ (kq * 4);
            Ws[kq*4+0][sw] = v.x; Ws[kq*4+1][sw] = v.y;
            Ws[kq*4+2][sw] = v.z; Ws[kq*4+3][sw] = v.w;
        }
        {
            int m = tid >> 3, kq = tid & 7, mg = m0 + m;
            float4 v = (mg < M) ? *(const float4*)&A[(size_t)mg * KDIM + k0 + kq * 4]
                                : make_float4(0.f,0.f,0.f,0.f);
            As[kq*4+0][m] = v.x; As[kq*4+1][m] = v.y;
            As[kq*4+2][m] = v.z; As[kq*4+3][m] = v.w;
        }
        __syncthreads();
#pragma unroll
        for (int k = 0; k < 32; k++) {
            int sk = k & 28;
            float2 av = *(const float2*)&As[k][tym * 2];
            ull a0 = splat2(av.x), a1 = splat2(av.y);
            int c1 = (txn * 8) ^ sk;
            ulonglong2 wA = *(const ulonglong2*)&Ws[k][c1];
            ulonglong2 wB = *(const ulonglong2*)&Ws[k][c1 ^ 4];
            fma2(acc[0][0], a0, wA.x); fma2(acc[0][1], a0, wA.y);
            fma2(acc[0][2], a0, wB.x); fma2(acc[0][3], a0, wB.y);
            fma2(acc[1][0], a1, wA.x); fma2(acc[1][1], a1, wA.y);
            fma2(acc[1][2], a1, wB.x); fma2(acc[1][3], a1, wB.y);
        }
    }
    const int n = n0 + txn * 8;
    float bs[8];
#pragma unroll
    for (int i = 0; i < 8; i++) {
        float b = b1 ? b1[n + i] : 0.f;
        if (b2) b += b2[n + i];
        bs[i] = b;
    }
#pragma unroll
    for (int m = 0; m < 2; m++) {
        int mg = m0 + tym * 2 + m;
        if (mg < M) {
            float2 p0 = unpack2(acc[m][0]), p1 = unpack2(acc[m][1]);
            float2 p2 = unpack2(acc[m][2]), p3 = unpack2(acc[m][3]);
            *(float4*)&C[(size_t)mg * G4 + n]     = make_float4(p0.x+bs[0], p0.y+bs[1], p1.x+bs[2], p1.y+bs[3]);
            *(float4*)&C[(size_t)mg * G4 + n + 4] = make_float4(p2.x+bs[4], p2.y+bs[5], p3.x+bs[6], p3.y+bs[7]);
        }
    }
}

#define FMA_BLK(WV, HA, HB, J) { ull ws_ = splat2(WV);                      \
    fma2(acc[J][0], ws_, (HA).x); fma2(acc[J][1], ws_, (HA).y);             \
    fma2(acc[J][2], ws_, (HB).x); fma2(acc[J][3], ws_, (HB).y); }

__global__ __launch_bounds__(NTHR, 1) void k_run(
    const float* __restrict__ Whh, const float* __restrict__ Wout,
    const float* __restrict__ bout, float* __restrict__ out, int do_hc)
{
    extern __shared__ __align__(16) float sm[];
    float* hs  = sm;                 // [512][20]
    float* red = sm;                 // [512][36] (union with hs)
    float* gt  = sm + RED_F;         // [128][20]

    const int tid = threadIdx.x;
    const int bid = blockIdx.x;
    const int bt  = bid >> 4;                // batch-tile group 0..7
    const int b0  = bt * 16;
    const int u0  = (bid & 15) * 32;
    const int v0  = (bid & 15) * 64;

    for (int t = 0; t < TT; t++) {
        const int rd = t & 1;

        // ---------- stage h[rd] -> hs[k][b] (stride 20) ----------
        {
            const float* hsrc = g_h[rd];
            const int kb = tid & 127, bq = tid >> 7;
#pragma unroll
            for (int i = 0; i < 4; i++) {
                int k = kb + 128 * i;
                float4 v;
                v.x = hsrc[(b0 + bq*4 + 0) * HID + k];
                v.y = hsrc[(b0 + bq*4 + 1) * HID + k];
                v.z = hsrc[(b0 + bq*4 + 2) * HID + k];
                v.w = hsrc[(b0 + bq*4 + 3) * HID + k];
                *(float4*)&hs[k * 20 + bq * 4] = v;
            }
        }
        __syncthreads();

        // ---------- Phase A main: 4 rows x 8 batches per thread, ksplit 8 ----------
        {
            const int s  = tid >> 6;
            const int bh = (tid >> 5) & 1;
            const int rg = tid & 31;
            const int wr0 = (rg >> 3) * HID + u0 + (rg & 7) * 4;
            const float* wp0 = Whh + (size_t)wr0 * KDIM + s * 64;
            const float* wp1 = wp0 + KDIM;
            const float* wp2 = wp1 + KDIM;
            const float* wp3 = wp2 + KDIM;
            const float* hb = hs + (s * 64) * 20 + bh * 8;
            ull acc[4][4];
#pragma unroll
            for (int j = 0; j < 4; j++)
#pragma unroll
                for (int p = 0; p < 4; p++) acc[j][p] = 0ull;

#pragma unroll 4
            for (int kk = 0; kk < 64; kk += 4) {
                float4 w0 = *(const float4*)(wp0 + kk);
                float4 w1 = *(const float4*)(wp1 + kk);
                float4 w2 = *(const float4*)(wp2 + kk);
                float4 w3 = *(const float4*)(wp3 + kk);
                const float* wa0 = (const float*)&w0;
                const float* wa1 = (const float*)&w1;
                const float* wa2 = (const float*)&w2;
                const float* wa3 = (const float*)&w3;
                const float* hk = hb + kk * 20;
#pragma unroll
                for (int jk = 0; jk < 4; jk++) {
                    ulonglong2 hA = *(const ulonglong2*)(hk + jk * 20);
                    ulonglong2 hB = *(const ulonglong2*)(hk + jk * 20 + 4);
                    FMA_BLK(wa0[jk], hA, hB, 0)
                    FMA_BLK(wa1[jk], hA, hB, 1)
                    FMA_BLK(wa2[jk], hA, hB, 2)
                    FMA_BLK(wa3[jk], hA, hB, 3)
                }
            }
            __syncthreads();                       // hs consumed
            ulonglong2* dst = (ulonglong2*)(red + tid * 36);
#pragma unroll
            for (int j = 0; j < 4; j++) {
                ulonglong2 a; a.x = acc[j][0]; a.y = acc[j][1]; dst[j*2]   = a;
                ulonglong2 b; b.x = acc[j][2]; b.y = acc[j][3]; dst[j*2+1] = b;
            }
        }
        __syncthreads();
        {   // reduce 8 partials -> gt[r][b]
            const int r = tid >> 2, bq = tid & 3;
            const int bh = bq >> 1, pr = bq & 1;
            const int Tb = bh * 32 + (r >> 2);
            const int off = (r & 3) * 8 + pr * 4;
            float4 sum = make_float4(0.f, 0.f, 0.f, 0.f);
#pragma unroll
            for (int s2 = 0; s2 < 8; s2++) {
                float4 v = *(const float4*)(red + (s2 * 64 + Tb) * 36 + off);
                sum.x += v.x; sum.y += v.y; sum.z += v.z; sum.w += v.w;
            }
            *(float4*)&gt[r * 20 + bq * 4] = sum;
        }
        __syncthreads();
        {   // LSTM elementwise: thread -> (b, u)
            const int b = tid >> 5, ul = tid & 31;
            const int bg = b0 + b, col = u0 + ul;
            const int tok = (int)(~(unsigned)g_pk[rd ^ 1][bg]);
            const float* bp = g_base + (size_t)bg * G4;
            const float* pp = g_P + (size_t)tok * G4;
            float gv[4];
#pragma unroll
            for (int g = 0; g < 4; g++)
                gv[g] = gt[(g * 32 + ul) * 20 + b] + bp[g * HID + col] + pp[g * HID + col];
            float c = g_c[bg * HID + col];
            float cn = sigf(gv[1]) * c + sigf(gv[0]) * tanhf(gv[2]);
            g_c[bg * HID + col] = cn;
            g_h[rd ^ 1][bg * HID + col] = sigf(gv[3]) * tanhf(cn);
        }
        if ((bid & 15) == 0 && tid < 16) g_pk[rd][b0 + tid] = 0ull;
        group_sync(bt);

        // ---------- stage h[rd^1] ----------
        {
            const float* hsrc = g_h[rd ^ 1];
            const int kb = tid & 127, bq = tid >> 7;
#pragma unroll
            for (int i = 0; i < 4; i++) {
                int k = kb + 128 * i;
                float4 v;
                v.x = hsrc[(b0 + bq*4 + 0) * HID + k];
                v.y = hsrc[(b0 + bq*4 + 1) * HID + k];
                v.z = hsrc[(b0 + bq*4 + 2) * HID + k];
                v.w = hsrc[(b0 + bq*4 + 3) * HID + k];
                *(float4*)&hs[k * 20 + bq * 4] = v;
            }
        }
        __syncthreads();

        // ---------- Phase B main: logits, 4 rows x 8 batches, ksplit 16 ----------
        {
            const int s  = tid >> 5;
            const int bh = (tid >> 4) & 1;
            const int rg = tid & 15;
            const int vr0 = v0 + rg * 4;
            const int r0c = (vr0 + 0 < VOCAB) ? vr0 + 0 : 0;
            const int r1c = (vr0 + 1 < VOCAB) ? vr0 + 1 : 0;
            const int r2c = (vr0 + 2 < VOCAB) ? vr0 + 2 : 0;
            const int r3c = (vr0 + 3 < VOCAB) ? vr0 + 3 : 0;
            const float* wp0 = Wout + (size_t)r0c * KDIM + s * 32;
            const float* wp1 = Wout + (size_t)r1c * KDIM + s * 32;
            const float* wp2 = Wout + (size_t)r2c * KDIM + s * 32;
            const float* wp3 = Wout + (size_t)r3c * KDIM + s * 32;
            const float* hb = hs + (s * 32) * 20 + bh * 8;
            ull acc[4][4];
#pragma unroll
            for (int j = 0; j < 4; j++)
#pragma unroll
                for (int p = 0; p < 4; p++) acc[j][p] = 0ull;

#pragma unroll 4
            for (int kk = 0; kk < 32; kk += 4) {
                float4 w0 = *(const float4*)(wp0 + kk);
                float4 w1 = *(const float4*)(wp1 + kk);
                float4 w2 = *(const float4*)(wp2 + kk);
                float4 w3 = *(const float4*)(wp3 + kk);
                const float* wa0 = (const float*)&w0;
                const float* wa1 = (const float*)&w1;
                const float* wa2 = (const float*)&w2;
                const float* wa3 = (const float*)&w3;
                const float* hk = hb + kk * 20;
#pragma unroll
                for (int jk = 0; jk < 4; jk++) {
                    ulonglong2 hA = *(const ulonglong2*)(hk + jk * 20);
                    ulonglong2 hB = *(const ulonglong2*)(hk + jk * 20 + 4);
                    FMA_BLK(wa0[jk], hA, hB, 0)
                    FMA_BLK(wa1[jk], hA, hB, 1)
                    FMA_BLK(wa2[jk], hA, hB, 2)
                    FMA_BLK(wa3[jk], hA, hB, 3)
                }
            }
            __syncthreads();
            ulonglong2* dst = (ulonglong2*)(red + tid * 36);
#pragma unroll
            for (int j = 0; j < 4; j++) {
                ulonglong2 a; a.x = acc[j][0]; a.y = acc[j][1]; dst[j*2]   = a;
                ulonglong2 b; b.x = acc[j][2]; b.y = acc[j][3]; dst[j*2+1] = b;
            }
        }
        __syncthreads();
        {   // reduce 16 partials -> gt[v][b] (+bias)
            const int vv = tid >> 3, bo = tid & 7;
            const int bh = bo >> 2, p = bo & 3;
            const int Tb = bh * 16 + (vv >> 2);
            const int off = (vv & 3) * 8 + p * 2;
            float sx = 0.f, sy = 0.f;
#pragma unroll
            for (int s2 = 0; s2 < 16; s2++) {
                float2 v = *(const float2*)(red + (s2 * 32 + Tb) * 36 + off);
                sx += v.x; sy += v.y;
            }
            float bo_ = (v0 + vv < VOCAB) ? bout[v0 + vv] : 0.f;
            gt[vv * 20 + bo * 2]     = sx + bo_;
            gt[vv * 20 + bo * 2 + 1] = sy + bo_;
        }
        __syncthreads();
        {   // store logits + argmax
            const int vl = tid & 63;
            const int vg = v0 + vl;
#pragma unroll
            for (int h2 = 0; h2 < 2; h2++) {
                const int b = (tid >> 6) + 8 * h2;
                float val = gt[vl * 20 + b];
                ull pk = 0ull;
                if (vg < VOCAB) {
                    out[((size_t)(b0 + b) * TT + t) * VOCAB + vg] = val;
                    pk = ((ull)fkey(val) << 32) | (unsigned)(~vg);
                }
#pragma unroll
                for (int sfl = 16; sfl; sfl >>= 1) {
                    ull o = __shfl_down_sync(0xffffffffu, pk, sfl);
                    if (o > pk) pk = o;
                }
                if ((tid & 31) == 0 && pk) atomicMax(&g_pk[rd][b0 + b], pk);
            }
        }
        group_sync(bt);
    }

    if (do_hc) {   // copy this block's own (b,u) slice of final h, c
        float* dst = out + (size_t)BB * TT * VOCAB;
        const int b = tid >> 5, ul = tid & 31;
        const int idx = (b0 + b) * HID + u0 + ul;
        dst[idx] = g_h[0][idx];
        dst[BB * HID + idx] = g_c[idx];
    }
}

extern "C" void kernel_launch(void* const* d_in, const int* in_sizes, int n_in,
                              void* d_out, int out_size) {
    const float* ctx  = (const float*)d_in[0];
    const float* emb  = (const float*)d_in[1];
    const float* Wih  = (const float*)d_in[2];
    const float* bih  = (const float*)d_in[3];
    const float* Whh  = (const float*)d_in[4];
    const float* bhh  = (const float*)d_in[5];
    const float* Wout = (const float*)d_in[6];
    const float* bout = (const float*)d_in[7];
    const int*   sid  = (const int*)d_in[8];
    float* out = (float*)d_out;

    static int smem_set = 0;
    if (!smem_set) {
        cudaFuncSetAttribute(k_run, cudaFuncAttributeMaxDynamicSharedMemorySize, SMEM_B);
        smem_set = 1;
    }

    k_init<<<256, 256>>>(ctx, sid);
    k_gemm<<<dim3(4, 16), 256>>>(ctx, BB, Wih, 1024, bih, bhh, 0);
    k_gemm<<<dim3(32, 16), 256>>>(emb, VOCAB, Wih + 512, 1024, (const float*)0, (const float*)0, 1);

    long long need = (long long)BB * TT * VOCAB + 2LL * BB * HID;
    int do_hc = ((long long)out_size >= need) ? 1 : 0;
    k_run<<<NBLK, NTHR, SMEM_B>>>(Whh, Wout, bout, out, do_hc);
}

// round 7
// speedup vs baseline: 1.6987x; 1.6987x over previous
#include <cuda_runtime.h>
#include <math.h>
#include <stdint.h>

#define BB    128
#define HID   512
#define G4    2048
#define VOCAB 1000
#define TT    256
#define KDIM  512
#define NBLK  128
#define NTHR  512

// smem floats: [0, 18432) hp(512x36) UNION red(512x34); [18432, 20992) gt(128x20)
#define RED_F   18432
#define GT_F    2560
#define SMEM_B  ((RED_F + GT_F) * 4)

typedef unsigned long long ull;

__device__ float g_base[BB * G4];
__device__ float g_P[VOCAB * G4];
__device__ float g_WhhT[KDIM * G4];        // [k][row]
__device__ float g_WoutT[KDIM * 1024];     // [k][v], zero-padded v>=1000
__device__ float g_h[2][BB * HID];
__device__ float g_c[BB * HID];
__device__ ull   g_pk[2][BB];
__device__ unsigned g_bcnt[8];
__device__ volatile unsigned g_bgen[8];

__device__ __forceinline__ ull splat2(float x) {
    ull r; asm("mov.b64 %0, {%1, %1};" : "=l"(r) : "f"(x)); return r;
}
__device__ __forceinline__ void fma2(ull& d, ull a, ull b) {
    asm("fma.rn.f32x2 %0, %1, %2, %0;" : "+l"(d) : "l"(a), "l"(b));
}
__device__ __forceinline__ float2 unpack2(ull x) {
    float lo, hi; asm("mov.b64 {%0, %1}, %2;" : "=f"(lo), "=f"(hi) : "l"(x));
    return make_float2(lo, hi);
}
__device__ __forceinline__ unsigned fkey(float f) {
    unsigned b = __float_as_uint(f);
    return (b & 0x80000000u) ? ~b : (b | 0x80000000u);
}
__device__ __forceinline__ float sigf(float x) { return 1.f / (1.f + expf(-x)); }

__device__ __forceinline__ void group_sync(int bt) {
    __syncthreads();
    if (threadIdx.x == 0) {
        unsigned g = g_bgen[bt];
        __threadfence();
        if (atomicAdd(&g_bcnt[bt], 1u) == 15u) {
            g_bcnt[bt] = 0u;
            __threadfence();
            g_bgen[bt] = g + 1u;
        } else {
            while (g_bgen[bt] == g) { }
        }
        __threadfence();
    }
    __syncthreads();
}

__global__ void k_init(const float* __restrict__ ctx, const int* __restrict__ sid) {
    int i = blockIdx.x * 256 + threadIdx.x;          // 65536
    g_h[0][i] = ctx[i];
    g_c[i] = 0.f;
    if (i < BB) {
        g_pk[0][i] = 0ull;
        g_pk[1][i] = (ull)(unsigned)(~(unsigned)sid[0]);
    }
    if (i < 8) { g_bcnt[i] = 0u; g_bgen[i] = 0u; }
}

// dst[c][r] = src[r][c]; dst is [C][Rpad], zero-fill r in [R, Rpad)
__global__ void k_transpose(const float* __restrict__ src, float* __restrict__ dst,
                            int R, int C, int Rpad) {
    __shared__ float tile[32][33];
    int c0 = blockIdx.x * 32, r0 = blockIdx.y * 32;
    int x = threadIdx.x, y = threadIdx.y;            // 32 x 8
#pragma unroll
    for (int i = 0; i < 32; i += 8) {
        int r = r0 + y + i, c = c0 + x;
        tile[y + i][x] = (r < R && c < C) ? src[(size_t)r * C + c] : 0.f;
    }
    __syncthreads();
#pragma unroll
    for (int i = 0; i < 32; i += 8) {
        int c = c0 + y + i, r = r0 + x;
        if (c < C && r < Rpad) dst[(size_t)c * Rpad + r] = tile[x][y + i];
    }
}

// one-time precompute: C[M,2048] = A[M,512] @ W^T (+b1+b2). tile 32m x 128n.
__global__ __launch_bounds__(256) void k_gemm(
    const float* __restrict__ A, int M,
    const float* __restrict__ W, int ws_,
    const float* __restrict__ b1, const float* __restrict__ b2, int dst)
{
    __shared__ __align__(16) float As[32][32];
    __shared__ __align__(16) float Ws[32][128];
    float* __restrict__ C = dst ? g_P : g_base;
    const int tid = threadIdx.x, txn = tid & 15, tym = tid >> 4;
    const int m0 = blockIdx.x * 32, n0 = blockIdx.y * 128;
    ull acc[2][4];
#pragma unroll
    for (int m = 0; m < 2; m++)
#pragma unroll
        for (int j = 0; j < 4; j++) acc[m][j] = 0ull;

    for (int k0 = 0; k0 < KDIM; k0 += 32) {
        __syncthreads();
#pragma unroll
        for (int i = 0; i < 4; i++) {
            int idx = i * 256 + tid, r = idx >> 3, kq = idx & 7;
            float4 v = *(const float4*)&W[(size_t)(n0 + r) * ws_ + k0 + kq * 4];
            int sw = r ^ (kq * 4);
            Ws[kq*4+0][sw] = v.x; Ws[kq*4+1][sw] = v.y;
            Ws[kq*4+2][sw] = v.z; Ws[kq*4+3][sw] = v.w;
        }
        {
            int m = tid >> 3, kq = tid & 7, mg = m0 + m;
            float4 v = (mg < M) ? *(const float4*)&A[(size_t)mg * KDIM + k0 + kq * 4]
                                : make_float4(0.f,0.f,0.f,0.f);
            As[kq*4+0][m] = v.x; As[kq*4+1][m] = v.y;
            As[kq*4+2][m] = v.z; As[kq*4+3][m] = v.w;
        }
        __syncthreads();
#pragma unroll
        for (int k = 0; k < 32; k++) {
            int sk = k & 28;
            float2 av = *(const float2*)&As[k][tym * 2];
            ull a0 = splat2(av.x), a1 = splat2(av.y);
            int c1 = (txn * 8) ^ sk;
            ulonglong2 wA = *(const ulonglong2*)&Ws[k][c1];
            ulonglong2 wB = *(const ulonglong2*)&Ws[k][c1 ^ 4];
            fma2(acc[0][0], a0, wA.x); fma2(acc[0][1], a0, wA.y);
            fma2(acc[0][2], a0, wB.x); fma2(acc[0][3], a0, wB.y);
            fma2(acc[1][0], a1, wA.x); fma2(acc[1][1], a1, wA.y);
            fma2(acc[1][2], a1, wB.x); fma2(acc[1][3], a1, wB.y);
        }
    }
    const int n = n0 + txn * 8;
    float bs[8];
#pragma unroll
    for (int i = 0; i < 8; i++) {
        float b = b1 ? b1[n + i] : 0.f;
        if (b2) b += b2[n + i];
        bs[i] = b;
    }
#pragma unroll
    for (int m = 0; m < 2; m++) {
        int mg = m0 + tym * 2 + m;
        if (mg < M) {
            float2 p0 = unpack2(acc[m][0]), p1 = unpack2(acc[m][1]);
            float2 p2 = unpack2(acc[m][2]), p3 = unpack2(acc[m][3]);
            *(float4*)&C[(size_t)mg * G4 + n]     = make_float4(p0.x+bs[0], p0.y+bs[1], p1.x+bs[2], p1.y+bs[3]);
            *(float4*)&C[(size_t)mg * G4 + n + 4] = make_float4(p2.x+bs[4], p2.y+bs[5], p3.x+bs[6], p3.y+bs[7]);
        }
    }
}

// inner micro-kernel: 4 rows (2 ull) x 8 paired batches per k
#define INNER_K(WPTR, HPTR) {                                                  \
    ulonglong2 w2 = *(const ulonglong2*)(WPTR);                                \
    const ulonglong2* hk = (const ulonglong2*)(HPTR);                          \
    _Pragma("unroll")                                                          \
    for (int j = 0; j < 4; j++) {                                              \
        ulonglong2 hb = hk[j];                                                 \
        fma2(acc[2*j][0],   hb.x, w2.x); fma2(acc[2*j][1],   hb.x, w2.y);      \
        fma2(acc[2*j+1][0], hb.y, w2.x); fma2(acc[2*j+1][1], hb.y, w2.y);      \
    } }

__global__ __launch_bounds__(NTHR, 1) void k_run(
    const float* __restrict__ bout, float* __restrict__ out, int do_hc)
{
    extern __shared__ __align__(16) float sm[];
    float* hp  = sm;                 // [512][36] paired h
    float* red = sm;                 // [512][34] partials (union)
    float* gt  = sm + RED_F;         // [128][20]

    const int tid = threadIdx.x;
    const int bid = blockIdx.x;
    const int bt  = bid >> 4;
    const int b0  = bt * 16;
    const int u0  = (bid & 15) * 32;
    const int v0  = (bid & 15) * 64;
    const int wrp = tid >> 5, lane = tid & 31;

    for (int t = 0; t < TT; t++) {
        const int rd = t & 1;

        // ---------- stage h[rd] -> hp[k][b] paired ----------
        {
            const float* hsrc = g_h[rd];
            const int k = tid;
#pragma unroll
            for (int b = 0; b < 16; b++) {
                float v = hsrc[(b0 + b) * HID + k];
                *(ull*)&hp[k * 36 + 2 * b] = splat2(v);
            }
        }
        __syncthreads();

        // ---------- Phase A main: gates GEMM ----------
        {
            const int s = wrp >> 1, bh = wrp & 1;
            const int wrow = (lane >> 3) * HID + u0 + (lane & 7) * 4;
            const float* wp  = g_WhhT + (size_t)(s * 64) * G4 + wrow;
            const float* hpp = hp + (s * 64) * 36 + bh * 16;
            ull acc[8][2];
#pragma unroll
            for (int i = 0; i < 8; i++) { acc[i][0] = 0ull; acc[i][1] = 0ull; }
#pragma unroll 4
            for (int kk = 0; kk < 64; kk++) {
                INNER_K(wp, hpp)
                wp += G4; hpp += 36;
            }
            __syncthreads();                   // hp consumed
            ull* dst = (ull*)(red + tid * 34);
#pragma unroll
            for (int bl = 0; bl < 8; bl++) { dst[bl*2] = acc[bl][0]; dst[bl*2+1] = acc[bl][1]; }
        }
        __syncthreads();
        {   // reduce over s=0..7 -> gt[r][b]
#pragma unroll
            for (int q = 0; q < 4; q++) {
                int o = tid + 512 * q;         // 2048 = 128r x 16b
                int r = o >> 4, b = o & 15;
                int g = r >> 5, ul = r & 31;
                int cc = g * 8 + (ul >> 2), rl = ul & 3;
                int off = (b & 7) * 4 + (rl >> 1) * 2 + (rl & 1);
                int bh = b >> 3;
                float sum = 0.f;
#pragma unroll
                for (int ss = 0; ss < 8; ss++)
                    sum += red[((ss * 2 + bh) * 32 + cc) * 34 + off];
                gt[r * 20 + b] = sum;
            }
        }
        __syncthreads();
        {   // LSTM elementwise
            const int b = tid >> 5, ul = tid & 31;
            const int bg = b0 + b, col = u0 + ul;
            const int tok = (int)(~(unsigned)g_pk[rd ^ 1][bg]);
            const float* bp = g_base + (size_t)bg * G4;
            const float* pp = g_P + (size_t)tok * G4;
            float gv[4];
#pragma unroll
            for (int g = 0; g < 4; g++)
                gv[g] = gt[(g * 32 + ul) * 20 + b] + bp[g * HID + col] + pp[g * HID + col];
            float c = g_c[bg * HID + col];
            float cn = sigf(gv[1]) * c + sigf(gv[0]) * tanhf(gv[2]);
            g_c[bg * HID + col] = cn;
            g_h[rd ^ 1][bg * HID + col] = sigf(gv[3]) * tanhf(cn);
        }
        if ((bid & 15) == 0 && tid < 16) g_pk[rd][b0 + tid] = 0ull;
        group_sync(bt);

        // ---------- stage h[rd^1] ----------
        {
            const float* hsrc = g_h[rd ^ 1];
            const int k = tid;
#pragma unroll
            for (int b = 0; b < 16; b++) {
                float v = hsrc[(b0 + b) * HID + k];
                *(ull*)&hp[k * 36 + 2 * b] = splat2(v);
            }
        }
        __syncthreads();

        // ---------- Phase B main: logits GEMM ----------
        {
            const int s = wrp;
            const int c = lane & 15, bh = lane >> 4;
            const int vr = v0 + c * 4;
            const float* wp  = g_WoutT + (size_t)(s * 32) * 1024 + vr;
            const float* hpp = hp + (s * 32) * 36 + bh * 16;
            ull acc[8][2];
#pragma unroll
            for (int i = 0; i < 8; i++) { acc[i][0] = 0ull; acc[i][1] = 0ull; }
#pragma unroll 4
            for (int kk = 0; kk < 32; kk++) {
                INNER_K(wp, hpp)
                wp += 1024; hpp += 36;
            }
            __syncthreads();
            ull* dst = (ull*)(red + tid * 34);
#pragma unroll
            for (int bl = 0; bl < 8; bl++) { dst[bl*2] = acc[bl][0]; dst[bl*2+1] = acc[bl][1]; }
        }
        __syncthreads();
        {   // reduce over s=0..15 -> gt[v][b] (+bias)
#pragma unroll
            for (int q = 0; q < 2; q++) {
                int o = tid + 512 * q;         // 1024 = 64v x 16b
                int vloc = o >> 4, b = o & 15;
                int cc = vloc >> 2, vl = vloc & 3;
                int off = (b & 7) * 4 + (vl >> 1) * 2 + (vl & 1);
                int bh = b >> 3;
                float sum = 0.f;
#pragma unroll
                for (int ss = 0; ss < 16; ss++)
                    sum += red[(ss * 32 + bh * 16 + cc) * 34 + off];
                int vg = v0 + vloc;
                float bo = (vg < VOCAB) ? bout[vg] : 0.f;
                gt[vloc * 20 + b] = sum + bo;
            }
        }
        __syncthreads();
        {   // store logits + argmax
            const int vl = tid & 63;
            const int vg = v0 + vl;
#pragma unroll
            for (int h2 = 0; h2 < 2; h2++) {
                const int b = (tid >> 6) + 8 * h2;
                float val = gt[vl * 20 + b];
                ull pk = 0ull;
                if (vg < VOCAB) {
                    out[((size_t)(b0 + b) * TT + t) * VOCAB + vg] = val;
                    pk = ((ull)fkey(val) << 32) | (unsigned)(~vg);
                }
#pragma unroll
                for (int sfl = 16; sfl; sfl >>= 1) {
                    ull o = __shfl_down_sync(0xffffffffu, pk, sfl);
                    if (o > pk) pk = o;
                }
                if ((tid & 31) == 0 && pk) atomicMax(&g_pk[rd][b0 + b], pk);
            }
        }
        group_sync(bt);
    }

    if (do_hc) {
        float* dst = out + (size_t)BB * TT * VOCAB;
        const int b = tid >> 5, ul = tid & 31;
        const int idx = (b0 + b) * HID + u0 + ul;
        dst[idx] = g_h[0][idx];
        dst[BB * HID + idx] = g_c[idx];
    }
}

extern "C" void kernel_launch(void* const* d_in, const int* in_sizes, int n_in,
                              void* d_out, int out_size) {
    const float* ctx  = (const float*)d_in[0];
    const float* emb  = (const float*)d_in[1];
    const float* Wih  = (const float*)d_in[2];
    const float* bih  = (const float*)d_in[3];
    const float* Whh  = (const float*)d_in[4];
    const float* bhh  = (const float*)d_in[5];
    const float* Wout = (const float*)d_in[6];
    const float* bout = (const float*)d_in[7];
    const int*   sid  = (const int*)d_in[8];
    float* out = (float*)d_out;

    static int smem_set = 0;
    if (!smem_set) {
        cudaFuncSetAttribute(k_run, cudaFuncAttributeMaxDynamicSharedMemorySize, SMEM_B);
        smem_set = 1;
    }

    float* whhT; cudaGetSymbolAddress((void**)&whhT, g_WhhT);
    float* woutT; cudaGetSymbolAddress((void**)&woutT, g_WoutT);

    k_init<<<256, 256>>>(ctx, sid);
    k_transpose<<<dim3(16, 64), dim3(32, 8)>>>(Whh, whhT, G4, KDIM, G4);
    k_transpose<<<dim3(16, 32), dim3(32, 8)>>>(Wout, woutT, VOCAB, KDIM, 1024);
    k_gemm<<<dim3(4, 16), 256>>>(ctx, BB, Wih, 1024, bih, bhh, 0);
    k_gemm<<<dim3(32, 16), 256>>>(emb, VOCAB, Wih + 512, 1024, (const float*)0, (const float*)0, 1);

    long long need = (long long)BB * TT * VOCAB + 2LL * BB * HID;
    int do_hc = ((long long)out_size >= need) ? 1 : 0;
    k_run<<<NBLK, NTHR, SMEM_B>>>(bout, out, do_hc);
}

// round 8
// speedup vs baseline: 1.7739x; 1.0442x over previous
#include <cuda_runtime.h>
#include <math.h>
#include <stdint.h>

#define BB    128
#define HID   512
#define G4    2048
#define VOCAB 1000
#define TT    256
#define KDIM  512
#define NBLK  128
#define NTHR  512

// smem floats: hp [0,18432) (stride36, alias Ared stride34) | Bred [18432,35840) | gt [35840,38400)
#define BRED_F  18432
#define GT_F0   35840
#define SMEM_B  (38400 * 4)

typedef unsigned long long ull;

__device__ float g_base[BB * G4];
__device__ float g_P[VOCAB * G4];
__device__ float g_WhhT[KDIM * G4];        // [k][row]
__device__ float g_WoutT[KDIM * 1024];     // [k][v], zero-padded v>=1000
__device__ float g_h[2][BB * HID];
__device__ float g_c[BB * HID];
__device__ ull   g_pk[2][BB];
__device__ unsigned g_bcnt[8];
__device__ volatile unsigned g_bgen[8];

__device__ __forceinline__ ull splat2(float x) {
    ull r; asm("mov.b64 %0, {%1, %1};" : "=l"(r) : "f"(x)); return r;
}
__device__ __forceinline__ void fma2(ull& d, ull a, ull b) {
    asm("fma.rn.f32x2 %0, %1, %2, %0;" : "+l"(d) : "l"(a), "l"(b));
}
__device__ __forceinline__ float2 unpack2(ull x) {
    float lo, hi; asm("mov.b64 {%0, %1}, %2;" : "=f"(lo), "=f"(hi) : "l"(x));
    return make_float2(lo, hi);
}
__device__ __forceinline__ unsigned fkey(float f) {
    unsigned b = __float_as_uint(f);
    return (b & 0x80000000u) ? ~b : (b | 0x80000000u);
}
__device__ __forceinline__ float sigf(float x) { return 1.f / (1.f + expf(-x)); }

__device__ __forceinline__ void group_sync(int bt) {
    __syncthreads();
    if (threadIdx.x == 0) {
        unsigned g = g_bgen[bt];
        __threadfence();
        if (atomicAdd(&g_bcnt[bt], 1u) == 15u) {
            g_bcnt[bt] = 0u;
            __threadfence();
            g_bgen[bt] = g + 1u;
        } else {
            while (g_bgen[bt] == g) { }
        }
        __threadfence();
    }
    __syncthreads();
}

__global__ void k_init(const float* __restrict__ ctx, const int* __restrict__ sid) {
    int i = blockIdx.x * 256 + threadIdx.x;          // 65536
    g_h[0][i] = ctx[i];
    g_c[i] = 0.f;
    if (i < BB) {
        g_pk[0][i] = (ull)(unsigned)(~(unsigned)sid[0]);   // token consumed at iter 0
        g_pk[1][i] = 0ull;
    }
    if (i < 8) { g_bcnt[i] = 0u; g_bgen[i] = 0u; }
}

// dst[c][r] = src[r][c]; dst is [C][Rpad], zero-fill r in [R, Rpad)
__global__ void k_transpose(const float* __restrict__ src, float* __restrict__ dst,
                            int R, int C, int Rpad) {
    __shared__ float tile[32][33];
    int c0 = blockIdx.x * 32, r0 = blockIdx.y * 32;
    int x = threadIdx.x, y = threadIdx.y;            // 32 x 8
#pragma unroll
    for (int i = 0; i < 32; i += 8) {
        int r = r0 + y + i, c = c0 + x;
        tile[y + i][x] = (r < R && c < C) ? src[(size_t)r * C + c] : 0.f;
    }
    __syncthreads();
#pragma unroll
    for (int i = 0; i < 32; i += 8) {
        int c = c0 + y + i, r = r0 + x;
        if (c < C && r < Rpad) dst[(size_t)c * Rpad + r] = tile[x][y + i];
    }
}

// one-time precompute: C[M,2048] = A[M,512] @ W^T (+b1+b2). tile 32m x 128n.
__global__ __launch_bounds__(256) void k_gemm(
    const float* __restrict__ A, int M,
    const float* __restrict__ W, int ws_,
    const float* __restrict__ b1, const float* __restrict__ b2, int dst)
{
    __shared__ __align__(16) float As[32][32];
    __shared__ __align__(16) float Ws[32][128];
    float* __restrict__ C = dst ? g_P : g_base;
    const int tid = threadIdx.x, txn = tid & 15, tym = tid >> 4;
    const int m0 = blockIdx.x * 32, n0 = blockIdx.y * 128;
    ull acc[2][4];
#pragma unroll
    for (int m = 0; m < 2; m++)
#pragma unroll
        for (int j = 0; j < 4; j++) acc[m][j] = 0ull;

    for (int k0 = 0; k0 < KDIM; k0 += 32) {
        __syncthreads();
#pragma unroll
        for (int i = 0; i < 4; i++) {
            int idx = i * 256 + tid, r = idx >> 3, kq = idx & 7;
            float4 v = *(const float4*)&W[(size_t)(n0 + r) * ws_ + k0 + kq * 4];
            int sw = r ^ (kq * 4);
            Ws[kq*4+0][sw] = v.x; Ws[kq*4+1][sw] = v.y;
            Ws[kq*4+2][sw] = v.z; Ws[kq*4+3][sw] = v.w;
        }
        {
            int m = tid >> 3, kq = tid & 7, mg = m0 + m;
            float4 v = (mg < M) ? *(const float4*)&A[(size_t)mg * KDIM + k0 + kq * 4]
                                : make_float4(0.f,0.f,0.f,0.f);
            As[kq*4+0][m] = v.x; As[kq*4+1][m] = v.y;
            As[kq*4+2][m] = v.z; As[kq*4+3][m] = v.w;
        }
        __syncthreads();
#pragma unroll
        for (int k = 0; k < 32; k++) {
            int sk = k & 28;
            float2 av = *(const float2*)&As[k][tym * 2];
            ull a0 = splat2(av.x), a1 = splat2(av.y);
            int c1 = (txn * 8) ^ sk;
            ulonglong2 wA = *(const ulonglong2*)&Ws[k][c1];
            ulonglong2 wB = *(const ulonglong2*)&Ws[k][c1 ^ 4];
            fma2(acc[0][0], a0, wA.x); fma2(acc[0][1], a0, wA.y);
            fma2(acc[0][2], a0, wB.x); fma2(acc[0][3], a0, wB.y);
            fma2(acc[1][0], a1, wA.x); fma2(acc[1][1], a1, wA.y);
            fma2(acc[1][2], a1, wB.x); fma2(acc[1][3], a1, wB.y);
        }
    }
    const int n = n0 + txn * 8;
    float bs[8];
#pragma unroll
    for (int i = 0; i < 8; i++) {
        float b = b1 ? b1[n + i] : 0.f;
        if (b2) b += b2[n + i];
        bs[i] = b;
    }
#pragma unroll
    for (int m = 0; m < 2; m++) {
        int mg = m0 + tym * 2 + m;
        if (mg < M) {
            float2 p0 = unpack2(acc[m][0]), p1 = unpack2(acc[m][1]);
            float2 p2 = unpack2(acc[m][2]), p3 = unpack2(acc[m][3]);
            *(float4*)&C[(size_t)mg * G4 + n]     = make_float4(p0.x+bs[0], p0.y+bs[1], p1.x+bs[2], p1.y+bs[3]);
            *(float4*)&C[(size_t)mg * G4 + n + 4] = make_float4(p2.x+bs[4], p2.y+bs[5], p3.x+bs[6], p3.y+bs[7]);
        }
    }
}

// inner micro-kernel: 4 rows (2 ull) x 8 paired batches per k
#define INNER_K(WPTR, HPTR) {                                                  \
    ulonglong2 w2 = *(const ulonglong2*)(WPTR);                                \
    const ulonglong2* hk = (const ulonglong2*)(HPTR);                          \
    _Pragma("unroll")                                                          \
    for (int j = 0; j < 4; j++) {                                              \
        ulonglong2 hb = hk[j];                                                 \
        fma2(acc[2*j][0],   hb.x, w2.x); fma2(acc[2*j][1],   hb.x, w2.y);      \
        fma2(acc[2*j+1][0], hb.y, w2.x); fma2(acc[2*j+1][1], hb.y, w2.y);      \
    } }

__global__ __launch_bounds__(NTHR, 1) void k_run(
    const float* __restrict__ bout, float* __restrict__ out, int do_hc)
{
    extern __shared__ __align__(16) float sm[];
    float* hp   = sm;                 // [512][36] paired h (stride 36)
    float* Ared = sm;                 // [512][34] gates partials (alias hp)
    float* Bred = sm + BRED_F;        // [512][34] logits partials
    float* gt   = sm + GT_F0;         // [128][20]

    const int tid = threadIdx.x;
    const int bid = blockIdx.x;
    const int bt  = bid >> 4;
    const int b0  = bt * 16;
    const int u0  = (bid & 15) * 32;
    const int v0  = (bid & 15) * 64;
    const int wrp = tid >> 5, lane = tid & 31;

    for (int i = 0; i <= TT; i++) {
        const int ph = i & 1;             // h(i) lives in g_h[ph]

        // ---------- stage h(i) -> hp[k][b] paired ----------
        {
            const float* hsrc = g_h[ph];
            const int k = tid;
#pragma unroll
            for (int b = 0; b < 16; b++) {
                float v = hsrc[(b0 + b) * HID + k];
                *(ull*)&hp[k * 36 + 2 * b] = splat2(v);
            }
        }
        __syncthreads();

        // ---------- logits(h(i)) -> out[i-1], argmax -> g_pk[ph] ----------
        if (i > 0) {
            {
                const int s = wrp;
                const int c = lane & 15, bh = lane >> 4;
                const int vr = v0 + c * 4;
                const float* wp  = g_WoutT + (size_t)(s * 32) * 1024 + vr;
                const float* hpp = hp + (s * 32) * 36 + bh * 16;
                ull acc[8][2];
#pragma unroll
                for (int z = 0; z < 8; z++) { acc[z][0] = 0ull; acc[z][1] = 0ull; }
#pragma unroll 4
                for (int kk = 0; kk < 32; kk++) {
                    INNER_K(wp, hpp)
                    wp += 1024; hpp += 36;
                }
                ull* dst = (ull*)(Bred + tid * 34);
#pragma unroll
                for (int bl = 0; bl < 8; bl++) { dst[bl*2] = acc[bl][0]; dst[bl*2+1] = acc[bl][1]; }
            }
            __syncthreads();
            {   // reduce 16 partials -> gt[v][b] (+bias)
#pragma unroll
                for (int q = 0; q < 2; q++) {
                    int o = tid + 512 * q;
                    int vloc = o >> 4, b = o & 15;
                    int cc = vloc >> 2, vl = vloc & 3;
                    int off = (b & 7) * 4 + vl;
                    int bh2 = b >> 3;
                    float sum = 0.f;
#pragma unroll
                    for (int ss = 0; ss < 16; ss++)
                        sum += Bred[(ss * 32 + bh2 * 16 + cc) * 34 + off];
                    int vg = v0 + vloc;
                    float bo = (vg < VOCAB) ? bout[vg] : 0.f;
                    gt[vloc * 20 + b] = sum + bo;
                }
            }
            __syncthreads();
            {   // store logits + argmax (token published EARLY)
                const int vl2 = tid & 63;
                const int vg = v0 + vl2;
#pragma unroll
                for (int h2 = 0; h2 < 2; h2++) {
                    const int b = (tid >> 6) + 8 * h2;
                    float val = gt[vl2 * 20 + b];
                    ull pk = 0ull;
                    if (vg < VOCAB) {
                        out[((size_t)(b0 + b) * TT + (i - 1)) * VOCAB + vg] = val;
                        pk = ((ull)fkey(val) << 32) | (unsigned)(~vg);
                    }
#pragma unroll
                    for (int sfl = 16; sfl; sfl >>= 1) {
                        ull o = __shfl_down_sync(0xffffffffu, pk, sfl);
                        if (o > pk) pk = o;
                    }
                    if ((tid & 31) == 0 && pk) atomicMax(&g_pk[ph][b0 + b], pk);
                }
            }
        }

        // ---------- gates GEMM h(i) @ WhhT (long; hides token broadcast) ----------
        if (i < TT) {
            {
                const int s = wrp >> 1, bh = wrp & 1;
                const int wrow = (lane >> 3) * HID + u0 + (lane & 7) * 4;
                const float* wp  = g_WhhT + (size_t)(s * 64) * G4 + wrow;
                const float* hpp = hp + (s * 64) * 36 + bh * 16;
                ull acc[8][2];
#pragma unroll
                for (int z = 0; z < 8; z++) { acc[z][0] = 0ull; acc[z][1] = 0ull; }
#pragma unroll 4
                for (int kk = 0; kk < 64; kk++) {
                    INNER_K(wp, hpp)
                    wp += G4; hpp += 36;
                }
                __syncthreads();               // hp fully consumed
                ull* dst = (ull*)(Ared + tid * 34);
#pragma unroll
                for (int bl = 0; bl < 8; bl++) { dst[bl*2] = acc[bl][0]; dst[bl*2+1] = acc[bl][1]; }
            }
            __syncthreads();
            {   // reduce 8 partials -> gt[r][b]
#pragma unroll
                for (int q = 0; q < 4; q++) {
                    int o = tid + 512 * q;
                    int r = o >> 4, b = o & 15;
                    int g = r >> 5, ul = r & 31;
                    int cc = g * 8 + (ul >> 2), rl = ul & 3;
                    int off = (b & 7) * 4 + rl;
                    int bh2 = b >> 3;
                    float sum = 0.f;
#pragma unroll
                    for (int ss = 0; ss < 8; ss++)
                        sum += Ared[((ss * 2 + bh2) * 32 + cc) * 34 + off];
                    gt[r * 20 + b] = sum;
                }
            }
            __syncthreads();
        }

        group_sync(bt);                        // token (g_pk[ph]) visible group-wide

        if (i < TT) {
            // LSTM elementwise with freshly-published token
            const int b = tid >> 5, ul = tid & 31;
            const int bg = b0 + b, col = u0 + ul;
            const int tok = (int)(~(unsigned)g_pk[ph][bg]);
            const float* bp = g_base + (size_t)bg * G4;
            const float* pp = g_P + (size_t)tok * G4;
            float gv[4];
#pragma unroll
            for (int g = 0; g < 4; g++)
                gv[g] = gt[(g * 32 + ul) * 20 + b] + bp[g * HID + col] + pp[g * HID + col];
            float c = g_c[bg * HID + col];
            float cn = sigf(gv[1]) * c + sigf(gv[0]) * tanhf(gv[2]);
            g_c[bg * HID + col] = cn;
            g_h[ph ^ 1][bg * HID + col] = sigf(gv[3]) * tanhf(cn);
        }
        if ((bid & 15) == 0 && tid < 16) g_pk[ph ^ 1][b0 + tid] = 0ull;  // slot consumed last iter
        group_sync(bt);                        // h(i+1) + reset visible
    }

    if (do_hc) {
        float* dst = out + (size_t)BB * TT * VOCAB;
        const int b = tid >> 5, ul = tid & 31;
        const int idx = (b0 + b) * HID + u0 + ul;
        dst[idx] = g_h[0][idx];
        dst[BB * HID + idx] = g_c[idx];
    }
}

extern "C" void kernel_launch(void* const* d_in, const int* in_sizes, int n_in,
                              void* d_out, int out_size) {
    const float* ctx  = (const float*)d_in[0];
    const float* emb  = (const float*)d_in[1];
    const float* Wih  = (const float*)d_in[2];
    const float* bih  = (const float*)d_in[3];
    const float* Whh  = (const float*)d_in[4];
    const float* bhh  = (const float*)d_in[5];
    const float* Wout = (const float*)d_in[6];
    const float* bout = (const float*)d_in[7];
    const int*   sid  = (const int*)d_in[8];
    float* out = (float*)d_out;

    static int smem_set = 0;
    if (!smem_set) {
        cudaFuncSetAttribute(k_run, cudaFuncAttributeMaxDynamicSharedMemorySize, SMEM_B);
        smem_set = 1;
    }

    float* whhT; cudaGetSymbolAddress((void**)&whhT, g_WhhT);
    float* woutT; cudaGetSymbolAddress((void**)&woutT, g_WoutT);

    k_init<<<256, 256>>>(ctx, sid);
    k_transpose<<<dim3(16, 64), dim3(32, 8)>>>(Whh, whhT, G4, KDIM, G4);
    k_transpose<<<dim3(16, 32), dim3(32, 8)>>>(Wout, woutT, VOCAB, KDIM, 1024);
    k_gemm<<<dim3(4, 16), 256>>>(ctx, BB, Wih, 1024, bih, bhh, 0);
    k_gemm<<<dim3(32, 16), 256>>>(emb, VOCAB, Wih + 512, 1024, (const float*)0, (const float*)0, 1);

    long long need = (long long)BB * TT * VOCAB + 2LL * BB * HID;
    int do_hc = ((long long)out_size >= need) ? 1 : 0;
    k_run<<<NBLK, NTHR, SMEM_B>>>(bout, out, do_hc);
}

// round 10
// speedup vs baseline: 1.9632x; 1.1067x over previous
#include <cuda_runtime.h>
#include <math.h>
#include <stdint.h>

#define BB    128
#define HID   512
#define G4    2048
#define VOCAB 1000
#define TT    256
#define KDIM  512
#define NBLK  128
#define NTHR  512

// smem floats: hp[0,18432) (stride36, alias Ared st34) | Bred[18432,35840) | gt[35840,38400)
//              bb[38400,39424) | baseS[39424,41472)
#define BRED_F  18432
#define GT_F0   35840
#define BB_F0   38400
#define BASE_F0 39424
#define SMEM_B  (41472 * 4)

typedef unsigned long long ull;

__device__ float g_base[BB * G4];
__device__ float g_P[VOCAB * G4];
__device__ float g_WhhT[KDIM * G4];        // [k][row]
__device__ float g_WoutT[KDIM * 1024];     // [k][v], zero-padded v>=1000
__device__ float g_h[2][BB * HID];
__device__ float g_c[BB * HID];
__device__ ull   g_pk[2][BB];
__device__ unsigned g_tcnt[2][8];
__device__ unsigned g_bcnt[8];
__device__ volatile unsigned g_bgen[8];

__device__ __forceinline__ ull splat2(float x) {
    ull r; asm("mov.b64 %0, {%1, %1};" : "=l"(r) : "f"(x)); return r;
}
__device__ __forceinline__ void fma2(ull& d, ull a, ull b) {
    asm("fma.rn.f32x2 %0, %1, %2, %0;" : "+l"(d) : "l"(a), "l"(b));
}
__device__ __forceinline__ void fadd2(ull& d, ull a) {
    asm("add.rn.f32x2 %0, %0, %1;" : "+l"(d) : "l"(a));
}
__device__ __forceinline__ float2 unpack2(ull x) {
    float lo, hi; asm("mov.b64 {%0, %1}, %2;" : "=f"(lo), "=f"(hi) : "l"(x));
    return make_float2(lo, hi);
}
__device__ __forceinline__ unsigned fkey(float f) {
    unsigned b = __float_as_uint(f);
    return (b & 0x80000000u) ? ~b : (b | 0x80000000u);
}
__device__ __forceinline__ float sigf(float x) { return 1.f / (1.f + expf(-x)); }
__device__ __forceinline__ unsigned ldacq_u32(const unsigned* p) {
    unsigned v; asm volatile("ld.acquire.gpu.u32 %0, [%1];" : "=r"(v) : "l"(p)); return v;
}
__device__ __forceinline__ ull ldacq_u64(const ull* p) {
    ull v; asm volatile("ld.acquire.gpu.u64 %0, [%1];" : "=l"(v) : "l"(p)); return v;
}

__device__ __forceinline__ void group_sync(int bt) {
    __syncthreads();
    if (threadIdx.x == 0) {
        unsigned g = g_bgen[bt];
        __threadfence();
        if (atomicAdd(&g_bcnt[bt], 1u) == 15u) {
            g_bcnt[bt] = 0u;
            __threadfence();
            g_bgen[bt] = g + 1u;
        } else {
            while (g_bgen[bt] == g) { }
        }
        __threadfence();
    }
    __syncthreads();
}

__global__ void k_init(const float* __restrict__ ctx, const int* __restrict__ sid) {
    int i = blockIdx.x * 256 + threadIdx.x;          // 65536
    g_h[0][i] = ctx[i];
    g_c[i] = 0.f;
    if (i < BB) {
        g_pk[0][i] = (ull)(unsigned)(~(unsigned)sid[0]);   // token consumed at iter 0
        g_pk[1][i] = 0ull;
    }
    if (i < 8) {
        g_bcnt[i] = 0u; g_bgen[i] = 0u;
        g_tcnt[0][i] = 16u;                                // iter-0 token "already arrived"
        g_tcnt[1][i] = 0u;
    }
}

// dst[c][r] = src[r][c]; dst is [C][Rpad], zero-fill r in [R, Rpad)
__global__ void k_transpose(const float* __restrict__ src, float* __restrict__ dst,
                            int R, int C, int Rpad) {
    __shared__ float tile[32][33];
    int c0 = blockIdx.x * 32, r0 = blockIdx.y * 32;
    int x = threadIdx.x, y = threadIdx.y;            // 32 x 8
#pragma unroll
    for (int i = 0; i < 32; i += 8) {
        int r = r0 + y + i, c = c0 + x;
        tile[y + i][x] = (r < R && c < C) ? src[(size_t)r * C + c] : 0.f;
    }
    __syncthreads();
#pragma unroll
    for (int i = 0; i < 32; i += 8) {
        int c = c0 + y + i, r = r0 + x;
        if (c < C && r < Rpad) dst[(size_t)c * Rpad + r] = tile[x][y + i];
    }
}

// one-time precompute: C[M,2048] = A[M,512] @ W^T (+b1+b2). tile 32m x 128n.
__global__ __launch_bounds__(256) void k_gemm(
    const float* __restrict__ A, int M,
    const float* __restrict__ W, int ws_,
    const float* __restrict__ b1, const float* __restrict__ b2, int dst)
{
    __shared__ __align__(16) float As[32][32];
    __shared__ __align__(16) float Ws[32][128];
    float* __restrict__ C = dst ? g_P : g_base;
    const int tid = threadIdx.x, txn = tid & 15, tym = tid >> 4;
    const int m0 = blockIdx.x * 32, n0 = blockIdx.y * 128;
    ull acc[2][4];
#pragma unroll
    for (int m = 0; m < 2; m++)
#pragma unroll
        for (int j = 0; j < 4; j++) acc[m][j] = 0ull;

    for (int k0 = 0; k0 < KDIM; k0 += 32) {
        __syncthreads();
#pragma unroll
        for (int i = 0; i < 4; i++) {
            int idx = i * 256 + tid, r = idx >> 3, kq = idx & 7;
            float4 v = *(const float4*)&W[(size_t)(n0 + r) * ws_ + k0 + kq * 4];
            int sw = r ^ (kq * 4);
            Ws[kq*4+0][sw] = v.x; Ws[kq*4+1][sw] = v.y;
            Ws[kq*4+2][sw] = v.z; Ws[kq*4+3][sw] = v.w;
        }
        {
            int m = tid >> 3, kq = tid & 7, mg = m0 + m;
            float4 v = (mg < M) ? *(const float4*)&A[(size_t)mg * KDIM + k0 + kq * 4]
                                : make_float4(0.f,0.f,0.f,0.f);
            As[kq*4+0][m] = v.x; As[kq*4+1][m] = v.y;
            As[kq*4+2][m] = v.z; As[kq*4+3][m] = v.w;
        }
        __syncthreads();
#pragma unroll
        for (int k = 0; k < 32; k++) {
            int sk = k & 28;
            float2 av = *(const float2*)&As[k][tym * 2];
            ull a0 = splat2(av.x), a1 = splat2(av.y);
            int c1 = (txn * 8) ^ sk;
            ulonglong2 wA = *(const ulonglong2*)&Ws[k][c1];
            ulonglong2 wB = *(const ulonglong2*)&Ws[k][c1 ^ 4];
            fma2(acc[0][0], a0, wA.x); fma2(acc[0][1], a0, wA.y);
            fma2(acc[0][2], a0, wB.x); fma2(acc[0][3], a0, wB.y);
            fma2(acc[1][0], a1, wA.x); fma2(acc[1][1], a1, wA.y);
            fma2(acc[1][2], a1, wB.x); fma2(acc[1][3], a1, wB.y);
        }
    }
    const int n = n0 + txn * 8;
    float bs[8];
#pragma unroll
    for (int i = 0; i < 8; i++) {
        float b = b1 ? b1[n + i] : 0.f;
        if (b2) b += b2[n + i];
        bs[i] = b;
    }
#pragma unroll
    for (int m = 0; m < 2; m++) {
        int mg = m0 + tym * 2 + m;
        if (mg < M) {
            float2 p0 = unpack2(acc[m][0]), p1 = unpack2(acc[m][1]);
            float2 p2 = unpack2(acc[m][2]), p3 = unpack2(acc[m][3]);
            *(float4*)&C[(size_t)mg * G4 + n]     = make_float4(p0.x+bs[0], p0.y+bs[1], p1.x+bs[2], p1.y+bs[3]);
            *(float4*)&C[(size_t)mg * G4 + n + 4] = make_float4(p2.x+bs[4], p2.y+bs[5], p3.x+bs[6], p3.y+bs[7]);
        }
    }
}

// inner micro-kernel: 4 rows (2 ull) x 8 paired batches per k
#define INNER_K(WPTR, HPTR) {                                                  \
    ulonglong2 w2 = *(const ulonglong2*)(WPTR);                                \
    const ulonglong2* hk = (const ulonglong2*)(HPTR);                          \
    _Pragma("unroll")                                                          \
    for (int j = 0; j < 4; j++) {                                              \
        ulonglong2 hb = hk[j];                                                 \
        fma2(acc[2*j][0],   hb.x, w2.x); fma2(acc[2*j][1],   hb.x, w2.y);      \
        fma2(acc[2*j+1][0], hb.y, w2.x); fma2(acc[2*j+1][1], hb.y, w2.y);      \
    } }

__global__ __launch_bounds__(NTHR, 1) void k_run(
    const float* __restrict__ bout, float* __restrict__ out, int do_hc)
{
    extern __shared__ __align__(16) float sm[];
    float* hp    = sm;                 // [512][36] paired h (stride 36)
    float* Ared  = sm;                 // [512][34] gates partials (alias hp)
    float* Bred  = sm + BRED_F;        // [512][34] logits partials
    float* gt    = sm + GT_F0;         // [128][20]
    float* bb    = sm + BB_F0;         // [1024] bias (padded)
    float* baseS = sm + BASE_F0;       // [16][128] base slice

    const int tid = threadIdx.x;
    const int bid = blockIdx.x;
    const int bt  = bid >> 4;
    const int b0  = bt * 16;
    const int u0  = (bid & 15) * 32;
    const int v0  = (bid & 15) * 64;
    const int wrp = tid >> 5, lane = tid & 31;

    // one-time preload of loop invariants
#pragma unroll
    for (int q = 0; q < 2; q++) {
        int v = tid + 512 * q;
        bb[v] = (v < VOCAB) ? bout[v] : 0.f;
    }
#pragma unroll
    for (int q = 0; q < 4; q++) {
        int idx = tid + 512 * q;
        int b = idx >> 7, gl = idx & 127;
        baseS[idx] = g_base[(size_t)(b0 + b) * G4 + (gl >> 5) * HID + u0 + (gl & 31)];
    }

    for (int i = 0; i <= TT; i++) {
        const int ph = i & 1;             // h(i) lives in g_h[ph]

        // ---------- stage h(i) -> hp[k][b] paired ----------
        {
            const float* hsrc = g_h[ph];
            const int k = tid;
#pragma unroll
            for (int b = 0; b < 16; b++) {
                float v = hsrc[(b0 + b) * HID + k];
                *(ull*)&hp[k * 36 + 2 * b] = splat2(v);
            }
        }
        __syncthreads();

        // ---------- logits(h(i)) -> out[i-1], argmax partials -> g_pk[ph], EARLY arrive ----------
        if (i > 0) {
            {
                const int s = wrp;
                const int c = lane & 15, bh = lane >> 4;
                const int vr = v0 + c * 4;
                const float* wp  = g_WoutT + (size_t)(s * 32) * 1024 + vr;
                const float* hpp = hp + (s * 32) * 36 + bh * 16;
                ull acc[8][2];
#pragma unroll
                for (int z = 0; z < 8; z++) { acc[z][0] = 0ull; acc[z][1] = 0ull; }
#pragma unroll 4
                for (int kk = 0; kk < 32; kk++) {
                    INNER_K(wp, hpp)
                    wp += 1024; hpp += 36;
                }
                ull* dst = (ull*)(Bred + tid * 34);
#pragma unroll
                for (int bl = 0; bl < 8; bl++) { dst[bl*2] = acc[bl][0]; dst[bl*2+1] = acc[bl][1]; }
            }
            __syncthreads();
            {   // pair-reduce 16 partials -> gt[v][b] (+bias), 1 ull-task/thread
                const int b = tid & 15, vp = tid >> 4;          // vp 0..31
                const int cc = vp >> 1, vl0 = (vp & 1) * 2;
                const int bh2 = b >> 3;
                const int off = (b & 7) * 4 + vl0;
                ull sum = 0ull;
#pragma unroll
                for (int ss = 0; ss < 16; ss++)
                    fadd2(sum, *(const ull*)&Bred[(ss * 32 + bh2 * 16 + cc) * 34 + off]);
                const int vloc = vp * 2;
                float2 p = unpack2(sum);
                gt[vloc * 20 + b]       = p.x + bb[v0 + vloc];
                gt[(vloc + 1) * 20 + b] = p.y + bb[v0 + vloc + 1];
            }
            __syncthreads();
            {   // store logits + argmax (token published EARLY)
                const int vl2 = tid & 63;
                const int vg = v0 + vl2;
#pragma unroll
                for (int h2 = 0; h2 < 2; h2++) {
                    const int b = (tid >> 6) + 8 * h2;
                    float val = gt[vl2 * 20 + b];
                    ull pk = 0ull;
                    if (vg < VOCAB) {
                        out[((size_t)(b0 + b) * TT + (i - 1)) * VOCAB + vg] = val;
                        pk = ((ull)fkey(val) << 32) | (unsigned)(~vg);
                    }
#pragma unroll
                    for (int sfl = 16; sfl; sfl >>= 1) {
                        ull o = __shfl_down_sync(0xffffffffu, pk, sfl);
                        if (o > pk) pk = o;
                    }
                    if ((tid & 31) == 0 && pk) atomicMax(&g_pk[ph][b0 + b], pk);
                }
            }
            __syncthreads();                           // all warps' atomicMax issued
            if (tid == 0) { __threadfence(); atomicAdd(&g_tcnt[ph][bt], 1u); }
        }

        // ---------- gates GEMM h(i) @ WhhT (long; absorbs token skew) ----------
        if (i < TT) {
            {
                const int s = wrp >> 1, bh = wrp & 1;
                const int wrow = (lane >> 3) * HID + u0 + (lane & 7) * 4;
                const float* wp  = g_WhhT + (size_t)(s * 64) * G4 + wrow;
                const float* hpp = hp + (s * 64) * 36 + bh * 16;
                ull acc[8][2];
#pragma unroll
                for (int z = 0; z < 8; z++) { acc[z][0] = 0ull; acc[z][1] = 0ull; }
#pragma unroll 4
                for (int kk = 0; kk < 64; kk++) {
                    INNER_K(wp, hpp)
                    wp += G4; hpp += 36;
                }
                __syncthreads();               // hp fully consumed (Ared aliases it)
                ull* dst = (ull*)(Ared + tid * 34);
#pragma unroll
                for (int bl = 0; bl < 8; bl++) { dst[bl*2] = acc[bl][0]; dst[bl*2+1] = acc[bl][1]; }
            }
            __syncthreads();
            {   // pair-reduce 8 partials -> gt[r][b], 2 ull-tasks/thread
#pragma unroll
                for (int q = 0; q < 2; q++) {
                    const int tq = tid + 512 * q;              // 0..1023
                    const int b = tq & 15, rp = tq >> 4;       // rp 0..63
                    const int g = rp >> 4, p16 = rp & 15;
                    const int cc = g * 8 + (p16 >> 1);
                    const int rl0 = (p16 & 1) * 2;
                    const int bh2 = b >> 3;
                    const int off = (b & 7) * 4 + rl0;
                    ull sum = 0ull;
#pragma unroll
                    for (int ss = 0; ss < 8; ss++)
                        fadd2(sum, *(const ull*)&Ared[((ss * 2 + bh2) * 32 + cc) * 34 + off]);
                    const int r = g * 32 + (p16 >> 1) * 4 + rl0;
                    float2 p = unpack2(sum);
                    gt[r * 20 + b]       = p.x;
                    gt[(r + 1) * 20 + b] = p.y;
                }
            }
            __syncthreads();
            // token wait: arrivals happened before our ~5us gates GEMM -> near-free
            if (tid == 0) { while (ldacq_u32(&g_tcnt[ph][bt]) < 16u) { } }
            __syncthreads();
            {   // LSTM elementwise with token
                const int b = tid >> 5, ul = tid & 31;
                const int bg = b0 + b, col = u0 + ul;
                const int tok = (int)(~(unsigned)ldacq_u64(&g_pk[ph][bg]));
                const float* pp = g_P + (size_t)tok * G4;
                float gv[4];
#pragma unroll
                for (int g = 0; g < 4; g++)
                    gv[g] = gt[(g * 32 + ul) * 20 + b] + baseS[b * 128 + g * 32 + ul]
                          + pp[g * HID + col];
                float c = g_c[bg * HID + col];
                float cn = sigf(gv[1]) * c + sigf(gv[0]) * tanhf(gv[2]);
                g_c[bg * HID + col] = cn;
                g_h[ph ^ 1][bg * HID + col] = sigf(gv[3]) * tanhf(cn);
            }
        }
        if ((bid & 15) == 0) {                 // reset other-parity slots (consumed 2 iters ago)
            if (tid < 16) g_pk[ph ^ 1][b0 + tid] = 0ull;
            else if (tid == 16) g_tcnt[ph ^ 1][bt] = 0u;
        }
        group_sync(bt);                        // h(i+1) + resets visible group-wide
    }

    if (do_hc) {
        float* dst = out + (size_t)BB * TT * VOCAB;
        const int b = tid >> 5, ul = tid & 31;
        const int idx = (b0 + b) * HID + u0 + ul;
        dst[idx] = g_h[0][idx];
        dst[BB * HID + idx] = g_c[idx];
    }
}

extern "C" void kernel_launch(void* const* d_in, const int* in_sizes, int n_in,
                              void* d_out, int out_size) {
    const float* ctx  = (const float*)d_in[0];
    const float* emb  = (const float*)d_in[1];
    const float* Wih  = (const float*)d_in[2];
    const float* bih  = (const float*)d_in[3];
    const float* Whh  = (const float*)d_in[4];
    const float* bhh  = (const float*)d_in[5];
    const float* Wout = (const float*)d_in[6];
    const float* bout = (const float*)d_in[7];
    const int*   sid  = (const int*)d_in[8];
    float* out = (float*)d_out;

    static int smem_set = 0;
    if (!smem_set) {
        cudaFuncSetAttribute(k_run, cudaFuncAttributeMaxDynamicSharedMemorySize, SMEM_B);
        smem_set = 1;
    }

    float* whhT; cudaGetSymbolAddress((void**)&whhT, g_WhhT);
    float* woutT; cudaGetSymbolAddress((void**)&woutT, g_WoutT);

    k_init<<<256, 256>>>(ctx, sid);
    k_transpose<<<dim3(16, 64), dim3(32, 8)>>>(Whh, whhT, G4, KDIM, G4);
    k_transpose<<<dim3(16, 32), dim3(32, 8)>>>(Wout, woutT, VOCAB, KDIM, 1024);
    k_gemm<<<dim3(4, 16), 256>>>(ctx, BB, Wih, 1024, bih, bhh, 0);
    k_gemm<<<dim3(32, 16), 256>>>(emb, VOCAB, Wih + 512, 1024, (const float*)0, (const float*)0, 1);

    long long need = (long long)BB * TT * VOCAB + 2LL * BB * HID;
    int do_hc = ((long long)out_size >= need) ? 1 : 0;
    k_run<<<NBLK, NTHR, SMEM_B>>>(bout, out, do_hc);
}

// round 11
// speedup vs baseline: 2.1711x; 1.1059x over previous
#include <cuda_runtime.h>
#include <math.h>
#include <stdint.h>

#define BB    128
#define HID   512
#define G4    2048
#define VOCAB 1000
#define TT    256
#define KDIM  512
#define NBLK  128
#define NTHR  512

// smem floats: hp[0,18432) stride36 | ABred[18432,35840) stride34 (A and B partials, time-shared)
//              gt[35840,38400) | bb[38400,39424) | baseS[39424,41472)
#define ABRED_F 18432
#define GT_F0   35840
#define BB_F0   38400
#define BASE_F0 39424
#define SMEM_B  (41472 * 4)

typedef unsigned long long ull;

__device__ float g_base[BB * G4];
__device__ float g_P[VOCAB * G4];
__device__ float g_WhhT[KDIM * G4];        // [k][row]
__device__ float g_WoutT[KDIM * 1024];     // [k][v], zero-padded v>=1000
__device__ float g_h[2][BB * HID];
__device__ float g_c[BB * HID];
__device__ ull   g_pk[2][BB];
__device__ unsigned g_tcnt[2][8];
__device__ unsigned g_bcnt[8];
__device__ unsigned g_bgen[8];

__device__ __forceinline__ ull splat2(float x) {
    ull r; asm("mov.b64 %0, {%1, %1};" : "=l"(r) : "f"(x)); return r;
}
__device__ __forceinline__ void fma2(ull& d, ull a, ull b) {
    asm("fma.rn.f32x2 %0, %1, %2, %0;" : "+l"(d) : "l"(a), "l"(b));
}
__device__ __forceinline__ void fadd2(ull& d, ull a) {
    asm("add.rn.f32x2 %0, %0, %1;" : "+l"(d) : "l"(a));
}
__device__ __forceinline__ float2 unpack2(ull x) {
    float lo, hi; asm("mov.b64 {%0, %1}, %2;" : "=f"(lo), "=f"(hi) : "l"(x));
    return make_float2(lo, hi);
}
__device__ __forceinline__ unsigned fkey(float f) {
    unsigned b = __float_as_uint(f);
    return (b & 0x80000000u) ? ~b : (b | 0x80000000u);
}
__device__ __forceinline__ float sigf(float x) { return 1.f / (1.f + expf(-x)); }
__device__ __forceinline__ unsigned ldacq_u32(const unsigned* p) {
    unsigned v; asm volatile("ld.acquire.gpu.u32 %0, [%1];" : "=r"(v) : "l"(p)); return v;
}
__device__ __forceinline__ ull ldacq_u64(const ull* p) {
    ull v; asm volatile("ld.acquire.gpu.u64 %0, [%1];" : "=l"(v) : "l"(p)); return v;
}

// release-arrive / acquire-wait group barrier; consumers of cross-block data use
// ldacq or __ldcg, so no post-wait CCTL.IVALL fence is needed.
__device__ __forceinline__ void group_sync(int bt) {
    __syncthreads();
    if (threadIdx.x == 0) {
        unsigned g = g_bgen[bt];
        __threadfence();                               // release everything this block wrote
        if (atomicAdd(&g_bcnt[bt], 1u) == 15u) {
            g_bcnt[bt] = 0u;
            __threadfence();
            g_bgen[bt] = g + 1u;
        } else {
            while (ldacq_u32(&g_bgen[bt]) == g) { }
        }
    }
    __syncthreads();
}

__global__ void k_init(const float* __restrict__ ctx, const int* __restrict__ sid) {
    int i = blockIdx.x * 256 + threadIdx.x;          // 65536
    g_h[0][i] = ctx[i];
    g_c[i] = 0.f;
    if (i < BB) {
        g_pk[0][i] = (ull)(unsigned)(~(unsigned)sid[0]);   // token consumed at iter 0
        g_pk[1][i] = 0ull;
    }
    if (i < 8) {
        g_bcnt[i] = 0u; g_bgen[i] = 0u;
        g_tcnt[0][i] = 16u;                                // iter-0 token pre-arrived
        g_tcnt[1][i] = 0u;
    }
}

// dst[c][r] = src[r][c]; dst is [C][Rpad], zero-fill r in [R, Rpad)
__global__ void k_transpose(const float* __restrict__ src, float* __restrict__ dst,
                            int R, int C, int Rpad) {
    __shared__ float tile[32][33];
    int c0 = blockIdx.x * 32, r0 = blockIdx.y * 32;
    int x = threadIdx.x, y = threadIdx.y;            // 32 x 8
#pragma unroll
    for (int i = 0; i < 32; i += 8) {
        int r = r0 + y + i, c = c0 + x;
        tile[y + i][x] = (r < R && c < C) ? src[(size_t)r * C + c] : 0.f;
    }
    __syncthreads();
#pragma unroll
    for (int i = 0; i < 32; i += 8) {
        int c = c0 + y + i, r = r0 + x;
        if (c < C && r < Rpad) dst[(size_t)c * Rpad + r] = tile[x][y + i];
    }
}

// one-time precompute: C[M,2048] = A[M,512] @ W^T (+b1+b2). tile 32m x 128n.
__global__ __launch_bounds__(256) void k_gemm(
    const float* __restrict__ A, int M,
    const float* __restrict__ W, int ws_,
    const float* __restrict__ b1, const float* __restrict__ b2, int dst)
{
    __shared__ __align__(16) float As[32][32];
    __shared__ __align__(16) float Ws[32][128];
    float* __restrict__ C = dst ? g_P : g_base;
    const int tid = threadIdx.x, txn = tid & 15, tym = tid >> 4;
    const int m0 = blockIdx.x * 32, n0 = blockIdx.y * 128;
    ull acc[2][4];
#pragma unroll
    for (int m = 0; m < 2; m++)
#pragma unroll
        for (int j = 0; j < 4; j++) acc[m][j] = 0ull;

    for (int k0 = 0; k0 < KDIM; k0 += 32) {
        __syncthreads();
#pragma unroll
        for (int i = 0; i < 4; i++) {
            int idx = i * 256 + tid, r = idx >> 3, kq = idx & 7;
            float4 v = *(const float4*)&W[(size_t)(n0 + r) * ws_ + k0 + kq * 4];
            int sw = r ^ (kq * 4);
            Ws[kq*4+0][sw] = v.x; Ws[kq*4+1][sw] = v.y;
            Ws[kq*4+2][sw] = v.z; Ws[kq*4+3][sw] = v.w;
        }
        {
            int m = tid >> 3, kq = tid & 7, mg = m0 + m;
            float4 v = (mg < M) ? *(const float4*)&A[(size_t)mg * KDIM + k0 + kq * 4]
                                : make_float4(0.f,0.f,0.f,0.f);
            As[kq*4+0][m] = v.x; As[kq*4+1][m] = v.y;
            As[kq*4+2][m] = v.z; As[kq*4+3][m] = v.w;
        }
        __syncthreads();
#pragma unroll
        for (int k = 0; k < 32; k++) {
            int sk = k & 28;
            float2 av = *(const float2*)&As[k][tym * 2];
            ull a0 = splat2(av.x), a1 = splat2(av.y);
            int c1 = (txn * 8) ^ sk;
            ulonglong2 wA = *(const ulonglong2*)&Ws[k][c1];
            ulonglong2 wB = *(const ulonglong2*)&Ws[k][c1 ^ 4];
            fma2(acc[0][0], a0, wA.x); fma2(acc[0][1], a0, wA.y);
            fma2(acc[0][2], a0, wB.x); fma2(acc[0][3], a0, wB.y);
            fma2(acc[1][0], a1, wA.x); fma2(acc[1][1], a1, wA.y);
            fma2(acc[1][2], a1, wB.x); fma2(acc[1][3], a1, wB.y);
        }
    }
    const int n = n0 + txn * 8;
    float bs[8];
#pragma unroll
    for (int i = 0; i < 8; i++) {
        float b = b1 ? b1[n + i] : 0.f;
        if (b2) b += b2[n + i];
        bs[i] = b;
    }
#pragma unroll
    for (int m = 0; m < 2; m++) {
        int mg = m0 + tym * 2 + m;
        if (mg < M) {
            float2 p0 = unpack2(acc[m][0]), p1 = unpack2(acc[m][1]);
            float2 p2 = unpack2(acc[m][2]), p3 = unpack2(acc[m][3]);
            *(float4*)&C[(size_t)mg * G4 + n]     = make_float4(p0.x+bs[0], p0.y+bs[1], p1.x+bs[2], p1.y+bs[3]);
            *(float4*)&C[(size_t)mg * G4 + n + 4] = make_float4(p2.x+bs[4], p2.y+bs[5], p3.x+bs[6], p3.y+bs[7]);
        }
    }
}

// inner micro-kernel: 4 rows (2 ull) x 8 paired batches per k
#define INNER_K(WPTR, HPTR) {                                                  \
    ulonglong2 w2 = *(const ulonglong2*)(WPTR);                                \
    const ulonglong2* hk = (const ulonglong2*)(HPTR);                          \
    _Pragma("unroll")                                                          \
    for (int j = 0; j < 4; j++) {                                              \
        ulonglong2 hb = hk[j];                                                 \
        fma2(acc[2*j][0],   hb.x, w2.x); fma2(acc[2*j][1],   hb.x, w2.y);      \
        fma2(acc[2*j+1][0], hb.y, w2.x); fma2(acc[2*j+1][1], hb.y, w2.y);      \
    } }

__global__ __launch_bounds__(NTHR, 1) void k_run(
    const float* __restrict__ bout, float* __restrict__ out, int do_hc)
{
    extern __shared__ __align__(16) float sm[];
    float* hp    = sm;                 // [512][36] paired h
    float* abred = sm + ABRED_F;       // [512][34] partials (time-shared A/B)
    float* gt    = sm + GT_F0;         // [128][20] (phase B only)
    float* bb    = sm + BB_F0;         // [1024]
    float* baseS = sm + BASE_F0;       // [16][128]

    const int tid = threadIdx.x;
    const int bid = blockIdx.x;
    const int bt  = bid >> 4;
    const int b0  = bt * 16;
    const int u0  = (bid & 15) * 32;
    const int v0  = (bid & 15) * 64;
    const int wrp = tid >> 5, lane = tid & 31;

    // one-time preload of loop invariants (visible after iter-0's full sync)
#pragma unroll
    for (int q = 0; q < 2; q++) {
        int v = tid + 512 * q;
        bb[v] = (v < VOCAB) ? bout[v] : 0.f;
    }
#pragma unroll
    for (int q = 0; q < 4; q++) {
        int idx = tid + 512 * q;
        int b = idx >> 7, gl = idx & 127;
        baseS[idx] = g_base[(size_t)(b0 + b) * G4 + (gl >> 5) * HID + u0 + (gl & 31)];
    }

    for (int i = 0; i <= TT; i++) {
        const int ph = i & 1;             // h(i) lives in g_h[ph]

        // ---------- per-warp stage: slice k in [32*wrp, 32*wrp+32) ----------
        {
            const float* hsrc = g_h[ph] + (size_t)b0 * HID + (wrp * 32 + lane);
            ull* dstp = (ull*)&hp[(wrp * 32 + lane) * 36];
#pragma unroll
            for (int b = 0; b < 16; b++)
                dstp[b] = splat2(__ldcg(hsrc + b * HID));   // L1-bypass: fresh cross-block data
        }
        __syncwarp();

        if (i > 0) {
            // ---------- logits GEMM on OWN staged slice ----------
            {
                const int c = lane & 15, bh = lane >> 4;
                const int vr = v0 + c * 4;
                const float* wp  = g_WoutT + (size_t)(wrp * 32) * 1024 + vr;
                const float* hpp = hp + (wrp * 32) * 36 + bh * 16;
                ull acc[8][2];
#pragma unroll
                for (int z = 0; z < 8; z++) { acc[z][0] = 0ull; acc[z][1] = 0ull; }
#pragma unroll 4
                for (int kk = 0; kk < 32; kk++) {
                    INNER_K(wp, hpp)
                    wp += 1024; hpp += 36;
                }
                ull* dst = (ull*)(abred + tid * 34);
#pragma unroll
                for (int bl = 0; bl < 8; bl++) { dst[bl*2] = acc[bl][0]; dst[bl*2+1] = acc[bl][1]; }
            }
            __syncthreads();     // S2: B partials + FULL hp visible
            {   // pair-reduce 16 partials -> gt[v][b] (+bias)
                const int b = tid & 15, vp = tid >> 4;
                const int cc = vp >> 1, vl0 = (vp & 1) * 2;
                const int bh2 = b >> 3;
                const int off = (b & 7) * 4 + vl0;
                ull sum = 0ull;
#pragma unroll
                for (int ss = 0; ss < 16; ss++)
                    fadd2(sum, *(const ull*)&abred[(ss * 32 + bh2 * 16 + cc) * 34 + off]);
                const int vloc = vp * 2;
                float2 p = unpack2(sum);
                gt[vloc * 20 + b]       = p.x + bb[v0 + vloc];
                gt[(vloc + 1) * 20 + b] = p.y + bb[v0 + vloc + 1];
            }
            __syncthreads();     // S3: gt ready, abred free for gates partials
            {   // store logits + argmax (token published EARLY)
                const int vl2 = tid & 63;
                const int vg = v0 + vl2;
#pragma unroll
                for (int h2 = 0; h2 < 2; h2++) {
                    const int b = (tid >> 6) + 8 * h2;
                    float val = gt[vl2 * 20 + b];
                    ull pk = 0ull;
                    if (vg < VOCAB) {
                        out[((size_t)(b0 + b) * TT + (i - 1)) * VOCAB + vg] = val;
                        pk = ((ull)fkey(val) << 32) | (unsigned)(~vg);
                    }
#pragma unroll
                    for (int sfl = 16; sfl; sfl >>= 1) {
                        ull o = __shfl_down_sync(0xffffffffu, pk, sfl);
                        if (o > pk) pk = o;
                    }
                    if ((tid & 31) == 0 && pk) atomicMax(&g_pk[ph][b0 + b], pk);
                }
            }
            __syncthreads();     // S4: all atomicMax issued block-wide
            if (tid == 0) { __threadfence(); atomicAdd(&g_tcnt[ph][bt], 1u); }
        } else {
            __syncthreads();     // iter 0: full hp visible for gates
        }

        if (i < TT) {
            // ---------- gates GEMM (reads all hp slices; abred is free) ----------
            {
                const int s = wrp >> 1, bh = wrp & 1;
                const int wrow = (lane >> 3) * HID + u0 + (lane & 7) * 4;
                const float* wp  = g_WhhT + (size_t)(s * 64) * G4 + wrow;
                const float* hpp = hp + (s * 64) * 36 + bh * 16;
                ull acc[8][2];
#pragma unroll
                for (int z = 0; z < 8; z++) { acc[z][0] = 0ull; acc[z][1] = 0ull; }
#pragma unroll 4
                for (int kk = 0; kk < 64; kk++) {
                    INNER_K(wp, hpp)
                    wp += G4; hpp += 36;
                }
                ull* dst = (ull*)(abred + tid * 34);
#pragma unroll
                for (int bl = 0; bl < 8; bl++) { dst[bl*2] = acc[bl][0]; dst[bl*2+1] = acc[bl][1]; }
            }
            __syncthreads();     // S6: gates partials visible
            if (tid == 0) { while (ldacq_u32(&g_tcnt[ph][bt]) < 16u) { } }  // arrived ~5us ago
            __syncthreads();
            {   // LSTM elementwise with MERGED partial reduce (same summation order)
                const int b = tid >> 5, ul = tid & 31;
                const int bg = b0 + b, col = u0 + ul;
                const int tok = (int)(~(unsigned)ldacq_u64(&g_pk[ph][bg]));
                const float* pp = g_P + (size_t)tok * G4;
                const int bh2 = b >> 3;
                const int boff = (b & 7) * 4 + (ul & 3);
                const int ccq = ul >> 2;
                float gv[4];
#pragma unroll
                for (int g = 0; g < 4; g++) {
                    const float* src = abred + (size_t)(bh2 * 32 + g * 8 + ccq) * 34 + boff;
                    float s0 = 0.f;
#pragma unroll
                    for (int ss = 0; ss < 8; ss++)
                        s0 += src[ss * (64 * 34)];
                    gv[g] = s0 + baseS[b * 128 + g * 32 + ul] + pp[g * HID + col];
                }
                float c = g_c[bg * HID + col];
                float cn = sigf(gv[1]) * c + sigf(gv[0]) * tanhf(gv[2]);
                g_c[bg * HID + col] = cn;
                g_h[ph ^ 1][bg * HID + col] = sigf(gv[3]) * tanhf(cn);
            }
        }
        if ((bid & 15) == 0) {                 // reset other-parity slots (consumed 2 iters ago)
            if (tid < 16) g_pk[ph ^ 1][b0 + tid] = 0ull;
            else if (tid == 16) g_tcnt[ph ^ 1][bt] = 0u;
        }
        group_sync(bt);                        // h(i+1) + resets released group-wide
    }

    if (do_hc) {
        float* dst = out + (size_t)BB * TT * VOCAB;
        const int b = tid >> 5, ul = tid & 31;
        const int idx = (b0 + b) * HID + u0 + ul;
        dst[idx] = g_h[0][idx];
        dst[BB * HID + idx] = g_c[idx];
    }
}

extern "C" void kernel_launch(void* const* d_in, const int* in_sizes, int n_in,
                              void* d_out, int out_size) {
    const float* ctx  = (const float*)d_in[0];
    const float* emb  = (const float*)d_in[1];
    const float* Wih  = (const float*)d_in[2];
    const float* bih  = (const float*)d_in[3];
    const float* Whh  = (const float*)d_in[4];
    const float* bhh  = (const float*)d_in[5];
    const float* Wout = (const float*)d_in[6];
    const float* bout = (const float*)d_in[7];
    const int*   sid  = (const int*)d_in[8];
    float* out = (float*)d_out;

    static int smem_set = 0;
    if (!smem_set) {
        cudaFuncSetAttribute(k_run, cudaFuncAttributeMaxDynamicSharedMemorySize, SMEM_B);
        smem_set = 1;
    }

    float* whhT; cudaGetSymbolAddress((void**)&whhT, g_WhhT);
    float* woutT; cudaGetSymbolAddress((void**)&woutT, g_WoutT);

    k_init<<<256, 256>>>(ctx, sid);
    k_transpose<<<dim3(16, 64), dim3(32, 8)>>>(Whh, whhT, G4, KDIM, G4);
    k_transpose<<<dim3(16, 32), dim3(32, 8)>>>(Wout, woutT, VOCAB, KDIM, 1024);
    k_gemm<<<dim3(4, 16), 256>>>(ctx, BB, Wih, 1024, bih, bhh, 0);
    k_gemm<<<dim3(32, 16), 256>>>(emb, VOCAB, Wih + 512, 1024, (const float*)0, (const float*)0, 1);

    long long need = (long long)BB * TT * VOCAB + 2LL * BB * HID;
    int do_hc = ((long long)out_size >= need) ? 1 : 0;
    k_run<<<NBLK, NTHR, SMEM_B>>>(bout, out, do_hc);
}

// round 12
// speedup vs baseline: 2.2671x; 1.0442x over previous
#include <cuda_runtime.h>
#include <math.h>
#include <stdint.h>

#define BB    128
#define HID   512
#define G4    2048
#define VOCAB 1000
#define TT    256
#define KDIM  512
#define NBLK  128
#define NTHR  512

// smem floats: hp[0,18432) stride36 | ABred[18432,35840) stride34 | bb[35840,36864) | baseS[36864,38912)
#define ABRED_F 18432
#define BB_F0   35840
#define BASE_F0 36864
#define SMEM_B  (38912 * 4)

typedef unsigned long long ull;

__device__ float g_base[BB * G4];
__device__ float g_P[VOCAB * G4];
__device__ float g_WhhT[KDIM * G4];        // [k][row]
__device__ float g_WoutT[KDIM * 1024];     // [k][v], zero-padded v>=1000
__device__ float g_h[2][BB * HID];
__device__ float g_c[BB * HID];
__device__ ull   g_pk[2][BB];
__device__ unsigned g_tcnt[2][8];
__device__ unsigned g_bcnt[8];
__device__ unsigned g_bgen[8];

__device__ __forceinline__ ull splat2(float x) {
    ull r; asm("mov.b64 %0, {%1, %1};" : "=l"(r) : "f"(x)); return r;
}
__device__ __forceinline__ void fma2(ull& d, ull a, ull b) {
    asm("fma.rn.f32x2 %0, %1, %2, %0;" : "+l"(d) : "l"(a), "l"(b));
}
__device__ __forceinline__ void fadd2(ull& d, ull a) {
    asm("add.rn.f32x2 %0, %0, %1;" : "+l"(d) : "l"(a));
}
__device__ __forceinline__ float2 unpack2(ull x) {
    float lo, hi; asm("mov.b64 {%0, %1}, %2;" : "=f"(lo), "=f"(hi) : "l"(x));
    return make_float2(lo, hi);
}
__device__ __forceinline__ unsigned fkey(float f) {
    unsigned b = __float_as_uint(f);
    return (b & 0x80000000u) ? ~b : (b | 0x80000000u);
}
__device__ __forceinline__ float sigf(float x) { return 1.f / (1.f + expf(-x)); }
__device__ __forceinline__ unsigned ldacq_u32(const unsigned* p) {
    unsigned v; asm volatile("ld.acquire.gpu.u32 %0, [%1];" : "=r"(v) : "l"(p)); return v;
}
__device__ __forceinline__ ull ldacq_u64(const ull* p) {
    ull v; asm volatile("ld.acquire.gpu.u64 %0, [%1];" : "=l"(v) : "l"(p)); return v;
}

// release-arrive / acquire-wait group barrier
__device__ __forceinline__ void group_sync(int bt) {
    __syncthreads();
    if (threadIdx.x == 0) {
        unsigned g = g_bgen[bt];
        __threadfence();
        if (atomicAdd(&g_bcnt[bt], 1u) == 15u) {
            g_bcnt[bt] = 0u;
            __threadfence();
            g_bgen[bt] = g + 1u;
        } else {
            while (ldacq_u32(&g_bgen[bt]) == g) { }
        }
    }
    __syncthreads();
}

__global__ void k_init(const float* __restrict__ ctx, const int* __restrict__ sid) {
    int i = blockIdx.x * 256 + threadIdx.x;          // 65536
    g_h[0][i] = ctx[i];
    g_c[i] = 0.f;
    if (i < BB) {
        g_pk[0][i] = (ull)(unsigned)(~(unsigned)sid[0]);   // token consumed at iter 0
        g_pk[1][i] = 0ull;
    }
    if (i < 8) {
        g_bcnt[i] = 0u; g_bgen[i] = 0u;
        g_tcnt[0][i] = 16u;                                // iter-0 token pre-arrived
        g_tcnt[1][i] = 0u;
    }
}

// dst[c][r] = src[r][c]; dst is [C][Rpad], zero-fill r in [R, Rpad)
__global__ void k_transpose(const float* __restrict__ src, float* __restrict__ dst,
                            int R, int C, int Rpad) {
    __shared__ float tile[32][33];
    int c0 = blockIdx.x * 32, r0 = blockIdx.y * 32;
    int x = threadIdx.x, y = threadIdx.y;            // 32 x 8
#pragma unroll
    for (int i = 0; i < 32; i += 8) {
        int r = r0 + y + i, c = c0 + x;
        tile[y + i][x] = (r < R && c < C) ? src[(size_t)r * C + c] : 0.f;
    }
    __syncthreads();
#pragma unroll
    for (int i = 0; i < 32; i += 8) {
        int c = c0 + y + i, r = r0 + x;
        if (c < C && r < Rpad) dst[(size_t)c * Rpad + r] = tile[x][y + i];
    }
}

// one-time precompute: C[M,2048] = A[M,512] @ W^T (+b1+b2). tile 32m x 128n.
__global__ __launch_bounds__(256) void k_gemm(
    const float* __restrict__ A, int M,
    const float* __restrict__ W, int ws_,
    const float* __restrict__ b1, const float* __restrict__ b2, int dst)
{
    __shared__ __align__(16) float As[32][32];
    __shared__ __align__(16) float Ws[32][128];
    float* __restrict__ C = dst ? g_P : g_base;
    const int tid = threadIdx.x, txn = tid & 15, tym = tid >> 4;
    const int m0 = blockIdx.x * 32, n0 = blockIdx.y * 128;
    ull acc[2][4];
#pragma unroll
    for (int m = 0; m < 2; m++)
#pragma unroll
        for (int j = 0; j < 4; j++) acc[m][j] = 0ull;

    for (int k0 = 0; k0 < KDIM; k0 += 32) {
        __syncthreads();
#pragma unroll
        for (int i = 0; i < 4; i++) {
            int idx = i * 256 + tid, r = idx >> 3, kq = idx & 7;
            float4 v = *(const float4*)&W[(size_t)(n0 + r) * ws_ + k0 + kq * 4];
            int sw = r ^ (kq * 4);
            Ws[kq*4+0][sw] = v.x; Ws[kq*4+1][sw] = v.y;
            Ws[kq*4+2][sw] = v.z; Ws[kq*4+3][sw] = v.w;
        }
        {
            int m = tid >> 3, kq = tid & 7, mg = m0 + m;
            float4 v = (mg < M) ? *(const float4*)&A[(size_t)mg * KDIM + k0 + kq * 4]
                                : make_float4(0.f,0.f,0.f,0.f);
            As[kq*4+0][m] = v.x; As[kq*4+1][m] = v.y;
            As[kq*4+2][m] = v.z; As[kq*4+3][m] = v.w;
        }
        __syncthreads();
#pragma unroll
        for (int k = 0; k < 32; k++) {
            int sk = k & 28;
            float2 av = *(const float2*)&As[k][tym * 2];
            ull a0 = splat2(av.x), a1 = splat2(av.y);
            int c1 = (txn * 8) ^ sk;
            ulonglong2 wA = *(const ulonglong2*)&Ws[k][c1];
            ulonglong2 wB = *(const ulonglong2*)&Ws[k][c1 ^ 4];
            fma2(acc[0][0], a0, wA.x); fma2(acc[0][1], a0, wA.y);
            fma2(acc[0][2], a0, wB.x); fma2(acc[0][3], a0, wB.y);
            fma2(acc[1][0], a1, wA.x); fma2(acc[1][1], a1, wA.y);
            fma2(acc[1][2], a1, wB.x); fma2(acc[1][3], a1, wB.y);
        }
    }
    const int n = n0 + txn * 8;
    float bs[8];
#pragma unroll
    for (int i = 0; i < 8; i++) {
        float b = b1 ? b1[n + i] : 0.f;
        if (b2) b += b2[n + i];
        bs[i] = b;
    }
#pragma unroll
    for (int m = 0; m < 2; m++) {
        int mg = m0 + tym * 2 + m;
        if (mg < M) {
            float2 p0 = unpack2(acc[m][0]), p1 = unpack2(acc[m][1]);
            float2 p2 = unpack2(acc[m][2]), p3 = unpack2(acc[m][3]);
            *(float4*)&C[(size_t)mg * G4 + n]     = make_float4(p0.x+bs[0], p0.y+bs[1], p1.x+bs[2], p1.y+bs[3]);
            *(float4*)&C[(size_t)mg * G4 + n + 4] = make_float4(p2.x+bs[4], p2.y+bs[5], p3.x+bs[6], p3.y+bs[7]);
        }
    }
}

// inner micro-kernel: 4 rows (2 ull) x 8 paired batches per k
#define INNER_K(WPTR, HPTR) {                                                  \
    ulonglong2 w2 = *(const ulonglong2*)(WPTR);                                \
    const ulonglong2* hk = (const ulonglong2*)(HPTR);                          \
    _Pragma("unroll")                                                          \
    for (int j = 0; j < 4; j++) {                                              \
        ulonglong2 hb = hk[j];                                                 \
        fma2(acc[2*j][0],   hb.x, w2.x); fma2(acc[2*j][1],   hb.x, w2.y);      \
        fma2(acc[2*j+1][0], hb.y, w2.x); fma2(acc[2*j+1][1], hb.y, w2.y);      \
    } }

__global__ __launch_bounds__(NTHR, 1) void k_run(
    const float* __restrict__ bout, float* __restrict__ out, int do_hc)
{
    extern __shared__ __align__(16) float sm[];
    float* hp    = sm;                 // [512][36] paired h
    float* abred = sm + ABRED_F;       // [512][34] partials (time-shared A/B)
    float* bb    = sm + BB_F0;         // [1024]
    float* baseS = sm + BASE_F0;       // [16][128]

    const int tid = threadIdx.x;
    const int bid = blockIdx.x;
    const int bt  = bid >> 4;
    const int b0  = bt * 16;
    const int u0  = (bid & 15) * 32;
    const int v0  = (bid & 15) * 64;
    const int wrp = tid >> 5, lane = tid & 31;

    // one-time preload of loop invariants
#pragma unroll
    for (int q = 0; q < 2; q++) {
        int v = tid + 512 * q;
        bb[v] = (v < VOCAB) ? bout[v] : 0.f;
    }
#pragma unroll
    for (int q = 0; q < 4; q++) {
        int idx = tid + 512 * q;
        int b = idx >> 7, gl = idx & 127;
        baseS[idx] = g_base[(size_t)(b0 + b) * G4 + (gl >> 5) * HID + u0 + (gl & 31)];
    }

    for (int i = 0; i <= TT; i++) {
        const int ph = i & 1;             // h(i) lives in g_h[ph]

        // ---------- per-warp stage: slice k in [32*wrp, 32*wrp+32) ----------
        {
            const float* hsrc = g_h[ph] + (size_t)b0 * HID + (wrp * 32 + lane);
            ull* dstp = (ull*)&hp[(wrp * 32 + lane) * 36];
#pragma unroll
            for (int b = 0; b < 16; b++)
                dstp[b] = splat2(__ldcg(hsrc + b * HID));
        }
        __syncwarp();

        if (i > 0) {
            // ---------- logits GEMM on OWN staged slice ----------
            {
                const int c = lane & 15, bh = lane >> 4;
                const int vr = v0 + c * 4;
                const float* wp  = g_WoutT + (size_t)(wrp * 32) * 1024 + vr;
                const float* hpp = hp + (wrp * 32) * 36 + bh * 16;
                ull acc[8][2];
#pragma unroll
                for (int z = 0; z < 8; z++) { acc[z][0] = 0ull; acc[z][1] = 0ull; }
#pragma unroll 4
                for (int kk = 0; kk < 32; kk++) {
                    INNER_K(wp, hpp)
                    wp += 1024; hpp += 36;
                }
                ull* dst = (ull*)(abred + tid * 34);
#pragma unroll
                for (int bl = 0; bl < 8; bl++) { dst[bl*2] = acc[bl][0]; dst[bl*2+1] = acc[bl][1]; }
            }
            __syncthreads();     // S2: B partials + FULL hp visible
            {   // FUSED reduce + bias + store + argmax: warp = batch, lane = v-pair
                const int b = wrp;                       // 0..15
                const int cc = lane >> 1, vl0 = (lane & 1) * 2;
                const int bh2 = b >> 3;
                const int off = (b & 7) * 4 + vl0;
                ull sum = 0ull;
#pragma unroll
                for (int ss = 0; ss < 16; ss++)
                    fadd2(sum, *(const ull*)&abred[(ss * 32 + bh2 * 16 + cc) * 34 + off]);
                const int vg = v0 + lane * 2;
                float2 p = unpack2(sum);
                p.x += bb[vg]; p.y += bb[vg + 1];
                ull pk = 0ull;
                if (vg < VOCAB) {                        // VOCAB even: pair all-in or all-out
                    *(float2*)&out[((size_t)(b0 + b) * TT + (i - 1)) * VOCAB + vg] = p;
                    ull k1 = ((ull)fkey(p.x) << 32) | (unsigned)(~vg);
                    ull k2 = ((ull)fkey(p.y) << 32) | (unsigned)(~(vg + 1));
                    pk = (k1 > k2) ? k1 : k2;
                }
#pragma unroll
                for (int sfl = 16; sfl; sfl >>= 1) {
                    ull o = __shfl_down_sync(0xffffffffu, pk, sfl);
                    if (o > pk) pk = o;
                }
                if (lane == 0 && pk) atomicMax(&g_pk[ph][b0 + b], pk);
            }
            __syncthreads();     // S4: all atomicMax issued block-wide; abred free
            if (tid == 0) { __threadfence(); atomicAdd(&g_tcnt[ph][bt], 1u); }
        } else {
            __syncthreads();     // iter 0: full hp visible for gates
        }

        if (i < TT) {
            // ---------- gates GEMM (reads all hp slices) ----------
            {
                const int s = wrp >> 1, bh = wrp & 1;
                const int wrow = (lane >> 3) * HID + u0 + (lane & 7) * 4;
                const float* wp  = g_WhhT + (size_t)(s * 64) * G4 + wrow;
                const float* hpp = hp + (s * 64) * 36 + bh * 16;
                ull acc[8][2];
#pragma unroll
                for (int z = 0; z < 8; z++) { acc[z][0] = 0ull; acc[z][1] = 0ull; }
#pragma unroll 4
                for (int kk = 0; kk < 64; kk++) {
                    INNER_K(wp, hpp)
                    wp += G4; hpp += 36;
                }
                ull* dst = (ull*)(abred + tid * 34);
#pragma unroll
                for (int bl = 0; bl < 8; bl++) { dst[bl*2] = acc[bl][0]; dst[bl*2+1] = acc[bl][1]; }
            }
            // ---------- token acquire + prefetch BEFORE the barrier (latency hidden) ----------
            const int b = tid >> 5, ul = tid & 31;
            const int bg = b0 + b, col = u0 + ul;
            while (ldacq_u32(&g_tcnt[ph][bt]) < 16u) { }   // arrived ~5us ago: fast path
            const int tok = (int)(~(unsigned)ldacq_u64(&g_pk[ph][bg]));
            const float* pp = g_P + (size_t)tok * G4;
            float pf[4];
#pragma unroll
            for (int g = 0; g < 4; g++) pf[g] = pp[g * HID + col];
            float cold = g_c[bg * HID + col];
            __syncthreads();     // S6: gates partials visible (prefetch drained under barrier)
            {   // LSTM elementwise with merged partial reduce (same summation order)
                const int bh2 = b >> 3;
                const int boff = (b & 7) * 4 + (ul & 3);
                const int ccq = ul >> 2;
                float gv[4];
#pragma unroll
                for (int g = 0; g < 4; g++) {
                    const float* src = abred + (size_t)(bh2 * 32 + g * 8 + ccq) * 34 + boff;
                    float s0 = 0.f;
#pragma unroll
                    for (int ss = 0; ss < 8; ss++)
                        s0 += src[ss * (64 * 34)];
                    gv[g] = s0 + baseS[b * 128 + g * 32 + ul] + pf[g];
                }
                float cn = sigf(gv[1]) * cold + sigf(gv[0]) * tanhf(gv[2]);
                g_c[bg * HID + col] = cn;
                g_h[ph ^ 1][bg * HID + col] = sigf(gv[3]) * tanhf(cn);
            }
        }
        if ((bid & 15) == 0) {                 // reset other-parity slots (consumed 2 iters ago)
            if (tid < 16) g_pk[ph ^ 1][b0 + tid] = 0ull;
            else if (tid == 16) g_tcnt[ph ^ 1][bt] = 0u;
        }
        group_sync(bt);                        // h(i+1) + resets released group-wide
    }

    if (do_hc) {
        float* dst = out + (size_t)BB * TT * VOCAB;
        const int b = tid >> 5, ul = tid & 31;
        const int idx = (b0 + b) * HID + u0 + ul;
        dst[idx] = g_h[0][idx];
        dst[BB * HID + idx] = g_c[idx];
    }
}

extern "C" void kernel_launch(void* const* d_in, const int* in_sizes, int n_in,
                              void* d_out, int out_size) {
    const float* ctx  = (const float*)d_in[0];
    const float* emb  = (const float*)d_in[1];
    const float* Wih  = (const float*)d_in[2];
    const float* bih  = (const float*)d_in[3];
    const float* Whh  = (const float*)d_in[4];
    const float* bhh  = (const float*)d_in[5];
    const float* Wout = (const float*)d_in[6];
    const float* bout = (const float*)d_in[7];
    const int*   sid  = (const int*)d_in[8];
    float* out = (float*)d_out;

    static int smem_set = 0;
    if (!smem_set) {
        cudaFuncSetAttribute(k_run, cudaFuncAttributeMaxDynamicSharedMemorySize, SMEM_B);
        smem_set = 1;
    }

    float* whhT; cudaGetSymbolAddress((void**)&whhT, g_WhhT);
    float* woutT; cudaGetSymbolAddress((void**)&woutT, g_WoutT);

    k_init<<<256, 256>>>(ctx, sid);
    k_transpose<<<dim3(16, 64), dim3(32, 8)>>>(Whh, whhT, G4, KDIM, G4);
    k_transpose<<<dim3(16, 32), dim3(32, 8)>>>(Wout, woutT, VOCAB, KDIM, 1024);
    k_gemm<<<dim3(4, 16), 256>>>(ctx, BB, Wih, 1024, bih, bhh, 0);
    k_gemm<<<dim3(32, 16), 256>>>(emb, VOCAB, Wih + 512, 1024, (const float*)0, (const float*)0, 1);

    long long need = (long long)BB * TT * VOCAB + 2LL * BB * HID;
    int do_hc = ((long long)out_size >= need) ? 1 : 0;
    k_run<<<NBLK, NTHR, SMEM_B>>>(bout, out, do_hc);
}